// round 12
// baseline (speedup 1.0000x reference)
#include <cuda_runtime.h>
#include <cuda_bf16.h>
#include <math.h>

#define HIDDEN 64
#define BATCH  16
#define TSTEPS 16
#define NNPOS  4096
#define TILE_P 256
#define NTHREADS 1024

typedef unsigned int u32;

// ---- smem layout (bytes) ----
#define A_STRIDE 144            // 64 bf16 = 128B padded to 144 (conflict-free frags)
#define B_STRIDE 400            // 192 bf16 = 384B padded to 400
#define APLANE   (258 * A_STRIDE)          // 37152
#define BPLANE   (128 * B_STRIDE)          // 51200
#define OFF_A    0                          // 2 planes: hi, lo
#define OFF_B    (2 * APLANE)               // 74304; 2 planes
#define OFF_X    (OFF_B + 2 * BPLANE)       // 176704; 258 floats
#define OFF_WX   (OFF_X + 258 * 4)          // 177736; 128*3 floats
#define OFF_BIAS (OFF_WX + 128 * 3 * 4)     // 179272; 128 floats
#define SMEM_BYTES (OFF_BIAS + 512)         // 179784

// ---- persistent scratch ----
// weight image: [hs][plane][n][192] bf16, n-row: gate=(n>>3)&3, chl=(n>>5)*8+(n&7)
__device__ __align__(16) __nv_bfloat16 g_wimg[2 * 2 * 128 * 192];
__device__ __align__(16) __nv_bfloat16 g_hp[2][2][(size_t)BATCH * NNPOS * HIDDEN]; // [buf][plane][(b*NN+p)*64+ch]
__device__ __align__(16) float         g_c[(size_t)BATCH * NNPOS * HIDDEN];

__device__ __forceinline__ float sigm(float v)  { return 1.f / (1.f + __expf(-v)); }
__device__ __forceinline__ float tanhq(float v) { return 1.f - 2.f / (__expf(2.f * v) + 1.f); }

__device__ __forceinline__ void mma16816(float* c, const u32* a, const u32* bf) {
    asm volatile(
        "mma.sync.aligned.m16n8k16.row.col.f32.bf16.bf16.f32 "
        "{%0,%1,%2,%3},{%4,%5,%6,%7},{%8,%9},{%0,%1,%2,%3};"
        : "+f"(c[0]), "+f"(c[1]), "+f"(c[2]), "+f"(c[3])
        : "r"(a[0]), "r"(a[1]), "r"(a[2]), "r"(a[3]), "r"(bf[0]), "r"(bf[1]));
}

// ---- setup: weight image ----
__global__ void repack_img(const float* __restrict__ conv_w) {
    int idx = blockIdx.x * blockDim.x + threadIdx.x;
    if (idx >= 2 * 128 * 192) return;
    int hs  = idx / 24576;
    int rem = idx % 24576;
    int n = rem / 192, k = rem % 192;
    int gate = (n >> 3) & 3;
    int chl  = (n >> 5) * 8 + (n & 7);
    int oc = gate * 64 + hs * 32 + chl;
    int kh = k / 64, ic = k % 64;
    float w = conv_w[((oc * 65 + (ic + 1)) * 3 + kh) * 3 + 1];
    __nv_bfloat16 whi = __float2bfloat16(w);
    __nv_bfloat16 wlo = __float2bfloat16(w - __bfloat162float(whi));
    g_wimg[((size_t)(hs * 2 + 0) * 128 + n) * 192 + k] = whi;
    g_wimg[((size_t)(hs * 2 + 1) * 128 + n) * 192 + k] = wlo;
}

__global__ void zero_state() {
    size_t i = (size_t)blockIdx.x * blockDim.x + threadIdx.x;
    size_t stride = (size_t)gridDim.x * blockDim.x;
    const size_t nc = (size_t)BATCH * NNPOS * HIDDEN;
    for (size_t j = i; j < nc; j += stride) g_c[j] = 0.f;
    u32* h0 = (u32*)&g_hp[0][0][0];            // both planes of buf0 contiguous
    for (size_t j = i; j < nc; j += stride) h0[j] = 0u;
}

// ---- one timestep: 1024 threads, 32 warps, warp tile 32x32 ----
__global__ void __launch_bounds__(NTHREADS, 1)
lstm_step(const float* __restrict__ x, const float* __restrict__ conv_w,
          const float* __restrict__ conv_b, int t) {
    extern __shared__ unsigned char sm[];
    const int tid = threadIdx.x, wid = tid >> 5, lane = tid & 31;
    const int g = lane >> 2, tq = lane & 3;
    const int p0 = blockIdx.x * TILE_P;
    const int hs = blockIdx.y;
    const int b  = blockIdx.z;
    const int rd = t & 1, wr = rd ^ 1;

    // ---- stage B: 2 planes x 128 rows x 24 uint4 ----
    {
        const uint4* src = (const uint4*)(g_wimg + (size_t)hs * 2 * 128 * 192);
        #pragma unroll
        for (int m = tid; m < 2 * 128 * 24; m += NTHREADS) {
            int pl = m / 3072, r = (m % 3072) / 24, c = m % 24;
            *(uint4*)(sm + OFF_B + pl * BPLANE + r * B_STRIDE + c * 16) = src[m];
        }
    }
    // ---- stage A (h rows p0-1..p0+256): 2 planes x 258 rows x 8 uint4 ----
    {
        const uint4 z4 = make_uint4(0, 0, 0, 0);
        #pragma unroll
        for (int m = tid; m < 2 * 258 * 8; m += NTHREADS) {
            int pl = m / 2064, r = (m % 2064) / 8, c = m % 8;
            int pos = p0 - 1 + r;
            uint4 v = z4;
            if (pos >= 0 && pos < NNPOS)
                v = ((const uint4*)&g_hp[rd][pl][((size_t)b * NNPOS + pos) * 64])[c];
            *(uint4*)(sm + OFF_A + pl * APLANE + r * A_STRIDE + c * 16) = v;
        }
    }
    // ---- stage x, wx, bias ----
    if (tid < 258) {
        int pos = p0 - 1 + tid;
        ((float*)(sm + OFF_X))[tid] =
            (pos >= 0 && pos < NNPOS) ? x[((size_t)b * TSTEPS + t) * NNPOS + pos] : 0.f;
    }
    if (tid >= 896) {
        int n = tid - 896;
        int gate = (n >> 3) & 3;
        int chl  = (n >> 5) * 8 + (n & 7);
        int oc = gate * 64 + hs * 32 + chl;
        ((float*)(sm + OFF_BIAS))[n] = conv_b[oc];
        #pragma unroll
        for (int kh = 0; kh < 3; kh++)
            ((float*)(sm + OFF_WX))[n * 3 + kh] = conv_w[((oc * 65 + 0) * 3 + kh) * 3 + 1];
    }
    __syncthreads();

    // ---- mainloop: 32 warps, warp grid 8x4, warp tile 32x32 ----
    const int wm = wid >> 2, wn = wid & 3;
    float C[2][4][4];
    #pragma unroll
    for (int mt = 0; mt < 2; mt++)
        #pragma unroll
        for (int nt = 0; nt < 4; nt++)
            #pragma unroll
            for (int r = 0; r < 4; r++) C[mt][nt][r] = 0.f;

    const unsigned char* Arow = sm + OFF_A + (wm * 32 + g) * A_STRIDE + tq * 4;
    const unsigned char* Brow = sm + OFF_B + (wn * 32 + g) * B_STRIDE + tq * 4;

    #pragma unroll 1
    for (int kh = 0; kh < 3; kh++) {
        const unsigned char* Akh = Arow + kh * A_STRIDE;
        const unsigned char* Bkh = Brow + kh * 128;      // k += 64 -> 128 bytes
        #pragma unroll
        for (int kk = 0; kk < 4; kk++) {
            // B fragments for this kk: hi and lo planes (shared by both mt)
            u32 bh[4][2], bl[4][2];
            #pragma unroll
            for (int nt = 0; nt < 4; nt++) {
                const unsigned char* q = Bkh + nt * (8 * B_STRIDE) + kk * 32;
                bh[nt][0] = *(const u32*)q;
                bh[nt][1] = *(const u32*)(q + 16);
                bl[nt][0] = *(const u32*)(q + BPLANE);
                bl[nt][1] = *(const u32*)(q + BPLANE + 16);
            }
            #pragma unroll
            for (int mt = 0; mt < 2; mt++) {
                const unsigned char* p = Akh + mt * (16 * A_STRIDE) + kk * 32;
                u32 ah[4], al[4];
                ah[0] = *(const u32*)p;
                ah[1] = *(const u32*)(p + 8 * A_STRIDE);
                ah[2] = *(const u32*)(p + 16);
                ah[3] = *(const u32*)(p + 8 * A_STRIDE + 16);
                al[0] = *(const u32*)(p + APLANE);
                al[1] = *(const u32*)(p + APLANE + 8 * A_STRIDE);
                al[2] = *(const u32*)(p + APLANE + 16);
                al[3] = *(const u32*)(p + APLANE + 8 * A_STRIDE + 16);
                #pragma unroll
                for (int nt = 0; nt < 4; nt++) mma16816(C[mt][nt], ah, bh[nt]); // hi*hi
                #pragma unroll
                for (int nt = 0; nt < 4; nt++) mma16816(C[mt][nt], al, bh[nt]); // lo*hi
                #pragma unroll
                for (int nt = 0; nt < 4; nt++) mma16816(C[mt][nt], ah, bl[nt]); // hi*lo
            }
        }
    }

    // ---- epilogue: nt == gate (n = wn*32 + gate*8 + 2tq + lsb) ----
    const float* xs  = (const float*)(sm + OFF_X);
    const float* wxs = (const float*)(sm + OFF_WX);
    const float* bss = (const float*)(sm + OFF_BIAS);

    #pragma unroll
    for (int mt = 0; mt < 2; mt++) {
        #pragma unroll
        for (int rh = 0; rh < 2; rh++) {
            const int prow = wm * 32 + mt * 16 + g + rh * 8;
            const int pos  = p0 + prow;
            const float xm1 = xs[prow], x0 = xs[prow + 1], xp1 = xs[prow + 2];
            const int chl = wn * 8 + 2 * tq;
            const size_t base = ((size_t)b * NNPOS + pos) * 64 + hs * 32 + chl;
            float2 cold = *(const float2*)(g_c + base);
            float cc[2], hh[2];
            #pragma unroll
            for (int lsb = 0; lsb < 2; lsb++) {
                const int nb = wn * 32 + 2 * tq + lsb;
                float vi = C[mt][0][rh * 2 + lsb] + bss[nb]      + wxs[nb * 3]        * xm1 + wxs[nb * 3 + 1]        * x0 + wxs[nb * 3 + 2]        * xp1;
                float vf = C[mt][1][rh * 2 + lsb] + bss[nb + 8]  + wxs[(nb + 8) * 3]  * xm1 + wxs[(nb + 8) * 3 + 1]  * x0 + wxs[(nb + 8) * 3 + 2]  * xp1;
                float vo = C[mt][2][rh * 2 + lsb] + bss[nb + 16] + wxs[(nb + 16) * 3] * xm1 + wxs[(nb + 16) * 3 + 1] * x0 + wxs[(nb + 16) * 3 + 2] * xp1;
                float vg = C[mt][3][rh * 2 + lsb] + bss[nb + 24] + wxs[(nb + 24) * 3] * xm1 + wxs[(nb + 24) * 3 + 1] * x0 + wxs[(nb + 24) * 3 + 2] * xp1;
                float co = lsb ? cold.y : cold.x;
                float c2 = sigm(vf) * co + sigm(vi) * tanhq(vg);
                cc[lsb] = c2;
                hh[lsb] = sigm(vo) * tanhq(c2);
            }
            *(float2*)(g_c + base) = make_float2(cc[0], cc[1]);
            __nv_bfloat162 vhi, vlo;
            vhi.x = __float2bfloat16(hh[0]);
            vhi.y = __float2bfloat16(hh[1]);
            vlo.x = __float2bfloat16(hh[0] - __bfloat162float(vhi.x));
            vlo.y = __float2bfloat16(hh[1] - __bfloat162float(vhi.y));
            *(__nv_bfloat162*)&g_hp[wr][0][base] = vhi;
            *(__nv_bfloat162*)&g_hp[wr][1][base] = vlo;
        }
    }
}

// ---- final 1x1 conv + broadcast over TS (final h in buf 0) ----
__global__ void __launch_bounds__(256)
fc_kernel(const float* __restrict__ fc_w, const float* __restrict__ fc_b,
          float* __restrict__ out) {
    __shared__ float w_s[HIDDEN];
    int tid = threadIdx.x;
    if (tid < HIDDEN) w_s[tid] = fc_w[tid];
    __syncthreads();

    int b = blockIdx.y;
    int n = blockIdx.x * 256 + tid;
    const __nv_bfloat16* hhi = &g_hp[0][0][((size_t)b * NNPOS + n) * 64];
    const __nv_bfloat16* hlo = &g_hp[0][1][((size_t)b * NNPOS + n) * 64];
    float acc = fc_b[0];
    #pragma unroll
    for (int ch = 0; ch < HIDDEN; ch++)
        acc += (__bfloat162float(hhi[ch]) + __bfloat162float(hlo[ch])) * w_s[ch];

    #pragma unroll
    for (int t = 0; t < TSTEPS; t++)
        out[((size_t)b * TSTEPS + t) * NNPOS + n] = acc;
}

extern "C" void kernel_launch(void* const* d_in, const int* in_sizes, int n_in,
                              void* d_out, int out_size) {
    const float* x      = (const float*)d_in[0];  // [16,16,4096,1]
    const float* conv_w = (const float*)d_in[1];  // [256,65,3,3]
    const float* conv_b = (const float*)d_in[2];  // [256]
    const float* fc_w   = (const float*)d_in[3];  // [1,64,1,1]
    const float* fc_b   = (const float*)d_in[4];  // [1]
    float* out = (float*)d_out;                   // [16,16,4096,1]

    cudaFuncSetAttribute(lstm_step, cudaFuncAttributeMaxDynamicSharedMemorySize, SMEM_BYTES);

    repack_img<<<(2 * 128 * 192 + 255) / 256, 256>>>(conv_w);
    zero_state<<<1024, 256>>>();

    for (int t = 0; t < TSTEPS; t++)
        lstm_step<<<dim3(NNPOS / TILE_P, 2, BATCH), NTHREADS, SMEM_BYTES>>>(x, conv_w, conv_b, t);

    fc_kernel<<<dim3(NNPOS / 256, BATCH), 256>>>(fc_w, fc_b, out);
}

// round 13
// speedup vs baseline: 1.0692x; 1.0692x over previous
#include <cuda_runtime.h>
#include <cuda_bf16.h>
#include <math.h>

#define HIDDEN 64
#define BATCH  16
#define TSTEPS 16
#define NNPOS  4096
#define TILE_P 128
#define NTHREADS 512
#define NCTAS 128

typedef unsigned int u32;

// ---- smem layout (bytes) ----
#define A_STRIDE 144                 // 64 bf16 = 128B padded to 144 (conflict-free)
#define B_STRIDE 400                 // 192 bf16 = 384B padded to 400
#define APLANE2  (130 * A_STRIDE)    // 18720 (one plane, 130 rows)
#define ABUF     (2 * APLANE2)       // 37440 (hi+lo planes)
#define OFF_A    0                   // 2 buffers
#define OFF_B    (2 * ABUF)          // 74880
#define BPLANE   (128 * B_STRIDE)    // 51200
#define OFF_WX   (OFF_B + 2 * BPLANE)   // 177280; 128*3 floats
#define OFF_BIAS (OFF_WX + 1536)        // 178816; 128 floats
#define SMEM_BYTES (OFF_BIAS + 512)     // 179328

// ---- persistent scratch ----
__device__ __align__(16) __nv_bfloat16 g_wimg[2 * 2 * 128 * 192];
__device__ __align__(16) __nv_bfloat16 g_hp[2][2][(size_t)BATCH * NNPOS * HIDDEN]; // [buf][plane][(b*NN+p)*64+ch]
__device__ __align__(16) float         g_c[(size_t)BATCH * NNPOS * HIDDEN];
__device__ int          g_bar_count = 0;
__device__ volatile int g_bar_gen   = 0;

__device__ __forceinline__ float sigm(float v)  { return 1.f / (1.f + __expf(-v)); }
__device__ __forceinline__ float tanhq(float v) { return 1.f - 2.f / (__expf(2.f * v) + 1.f); }

__device__ __forceinline__ u32 smem_u32(const void* p) {
    u32 a; asm("{ .reg .u64 t; cvta.to.shared.u64 t, %1; cvt.u32.u64 %0, t; }" : "=r"(a) : "l"(p));
    return a;
}

__device__ __forceinline__ void mma16816(float* c, const u32* a, const u32* bf) {
    asm volatile(
        "mma.sync.aligned.m16n8k16.row.col.f32.bf16.bf16.f32 "
        "{%0,%1,%2,%3},{%4,%5,%6,%7},{%8,%9},{%0,%1,%2,%3};"
        : "+f"(c[0]), "+f"(c[1]), "+f"(c[2]), "+f"(c[3])
        : "r"(a[0]), "r"(a[1]), "r"(a[2]), "r"(a[3]), "r"(bf[0]), "r"(bf[1]));
}

// prefetch one A tile (2 planes x 130 rows x 8 chunks) via cp.async.cg (L1-bypass!)
__device__ __forceinline__ void prefetchA(u32 sbase, int buf, int b, int p0, int rd, int tid) {
    for (int m = tid; m < 2080; m += NTHREADS) {
        int pl = m / 1040, r = (m % 1040) / 8, c = m % 8;
        int pos = p0 - 1 + r;
        bool ok = (pos >= 0 && pos < NNPOS);
        int posc = ok ? pos : 0;
        const void* src = (const char*)&g_hp[rd][pl][((size_t)b * NNPOS + posc) * 64] + c * 16;
        u32 dst = sbase + OFF_A + buf * ABUF + pl * APLANE2 + r * A_STRIDE + c * 16;
        int sz = ok ? 16 : 0;
        asm volatile("cp.async.cg.shared.global [%0], [%1], 16, %2;" :: "r"(dst), "l"(src), "r"(sz));
    }
    asm volatile("cp.async.commit_group;" ::: "memory");
}

__device__ __forceinline__ void grid_barrier() {
    __syncthreads();
    if (threadIdx.x == 0) {
        __threadfence();                       // release our h/c writes
        int gen = g_bar_gen;
        if (atomicAdd(&g_bar_count, 1) == NCTAS - 1) {
            g_bar_count = 0;
            __threadfence();
            g_bar_gen = gen + 1;               // release
        } else {
            while (g_bar_gen == gen) { }
        }
        __threadfence();                       // acquire
    }
    __syncthreads();
}

// ---- setup: weight image ----
__global__ void repack_img(const float* __restrict__ conv_w) {
    int idx = blockIdx.x * blockDim.x + threadIdx.x;
    if (idx >= 2 * 128 * 192) return;
    int hs  = idx / 24576;
    int rem = idx % 24576;
    int n = rem / 192, k = rem % 192;
    int gate = (n >> 3) & 3;
    int chl  = (n >> 5) * 8 + (n & 7);
    int oc = gate * 64 + hs * 32 + chl;
    int kh = k / 64, ic = k % 64;
    float w = conv_w[((oc * 65 + (ic + 1)) * 3 + kh) * 3 + 1];
    __nv_bfloat16 whi = __float2bfloat16(w);
    __nv_bfloat16 wlo = __float2bfloat16(w - __bfloat162float(whi));
    g_wimg[((size_t)(hs * 2 + 0) * 128 + n) * 192 + k] = whi;
    g_wimg[((size_t)(hs * 2 + 1) * 128 + n) * 192 + k] = wlo;
}

__global__ void zero_state() {
    size_t i = (size_t)blockIdx.x * blockDim.x + threadIdx.x;
    size_t stride = (size_t)gridDim.x * blockDim.x;
    const size_t nc = (size_t)BATCH * NNPOS * HIDDEN;
    for (size_t j = i; j < nc; j += stride) g_c[j] = 0.f;
    u32* h0 = (u32*)&g_hp[0][0][0];            // both planes of buf0 contiguous
    for (size_t j = i; j < nc; j += stride) h0[j] = 0u;
}

// ---- persistent kernel: all 16 timesteps, 128 CTAs, software grid barrier ----
__global__ void __launch_bounds__(NTHREADS, 1)
lstm_persist(const float* __restrict__ x, const float* __restrict__ conv_w,
             const float* __restrict__ conv_b) {
    extern __shared__ unsigned char sm[];
    const u32 sbase = smem_u32(sm);
    const int tid = threadIdx.x, wid = tid >> 5, lane = tid & 31;
    const int g = lane >> 2, tq = lane & 3;
    const int ci = blockIdx.x;            // 0..63
    const int hs = blockIdx.y;            // 0..1
    const int wm = wid >> 2, wn = wid & 3;

    // ---- stage B once: 2 planes x 128 rows x 24 uint4 ----
    {
        const uint4* src = (const uint4*)(g_wimg + (size_t)hs * 2 * 128 * 192);
        #pragma unroll
        for (int m = tid; m < 2 * 128 * 24; m += NTHREADS) {
            int pl = m / 3072, r = (m % 3072) / 24, c = m % 24;
            *(uint4*)(sm + OFF_B + pl * BPLANE + r * B_STRIDE + c * 16) = src[m];
        }
    }
    // ---- stage bias/wx once ----
    if (tid < 128) {
        int n = tid;
        int gate = (n >> 3) & 3;
        int chl  = (n >> 5) * 8 + (n & 7);
        int oc = gate * 64 + hs * 32 + chl;
        ((float*)(sm + OFF_BIAS))[n] = conv_b[oc];
        #pragma unroll
        for (int kh = 0; kh < 3; kh++)
            ((float*)(sm + OFF_WX))[n * 3 + kh] = conv_w[((oc * 65 + 0) * 3 + kh) * 3 + 1];
    }

    const float* wxs = (const float*)(sm + OFF_WX);
    const float* bss = (const float*)(sm + OFF_BIAS);
    int buf = 0;

    #pragma unroll 1
    for (int t = 0; t < TSTEPS; t++) {
        const int rd = t & 1, wr = rd ^ 1;

        // prefetch item 0 of this step (h[rd] is ready: barrier or t=0 zero-init)
        {
            int wi = ci * 8;
            prefetchA(sbase, buf, wi >> 5, (wi & 31) * TILE_P, rd, tid);
        }
        asm volatile("cp.async.wait_group 0;" ::: "memory");
        __syncthreads();

        #pragma unroll 1
        for (int i = 0; i < 8; i++) {
            const int wi = ci * 8 + i;
            const int b  = wi >> 5;
            const int p0 = (wi & 31) * TILE_P;

            // lookahead prefetch into the other buffer
            if (i < 7) {
                int wj = wi + 1;
                prefetchA(sbase, buf ^ 1, wj >> 5, (wj & 31) * TILE_P, rd, tid);
            }

            // ---- mainloop: warp tile 32x32, fused hi*hi + lo*hi + hi*lo ----
            float C[2][4][4];
            #pragma unroll
            for (int mt = 0; mt < 2; mt++)
                #pragma unroll
                for (int nt = 0; nt < 4; nt++)
                    #pragma unroll
                    for (int r = 0; r < 4; r++) C[mt][nt][r] = 0.f;

            const unsigned char* Arow = sm + OFF_A + buf * ABUF + (wm * 32 + g) * A_STRIDE + tq * 4;
            const unsigned char* Brow = sm + OFF_B + (wn * 32 + g) * B_STRIDE + tq * 4;

            #pragma unroll 1
            for (int kh = 0; kh < 3; kh++) {
                const unsigned char* Akh = Arow + kh * A_STRIDE;
                const unsigned char* Bkh = Brow + kh * 128;
                #pragma unroll
                for (int kk = 0; kk < 4; kk++) {
                    u32 bh[4][2], bl[4][2];
                    #pragma unroll
                    for (int nt = 0; nt < 4; nt++) {
                        const unsigned char* q = Bkh + nt * (8 * B_STRIDE) + kk * 32;
                        bh[nt][0] = *(const u32*)q;
                        bh[nt][1] = *(const u32*)(q + 16);
                        bl[nt][0] = *(const u32*)(q + BPLANE);
                        bl[nt][1] = *(const u32*)(q + BPLANE + 16);
                    }
                    #pragma unroll
                    for (int mt = 0; mt < 2; mt++) {
                        const unsigned char* p = Akh + mt * (16 * A_STRIDE) + kk * 32;
                        u32 ah[4], al[4];
                        ah[0] = *(const u32*)p;
                        ah[1] = *(const u32*)(p + 8 * A_STRIDE);
                        ah[2] = *(const u32*)(p + 16);
                        ah[3] = *(const u32*)(p + 8 * A_STRIDE + 16);
                        al[0] = *(const u32*)(p + APLANE2);
                        al[1] = *(const u32*)(p + APLANE2 + 8 * A_STRIDE);
                        al[2] = *(const u32*)(p + APLANE2 + 16);
                        al[3] = *(const u32*)(p + APLANE2 + 8 * A_STRIDE + 16);
                        #pragma unroll
                        for (int nt = 0; nt < 4; nt++) mma16816(C[mt][nt], ah, bh[nt]);
                        #pragma unroll
                        for (int nt = 0; nt < 4; nt++) mma16816(C[mt][nt], al, bh[nt]);
                        #pragma unroll
                        for (int nt = 0; nt < 4; nt++) mma16816(C[mt][nt], ah, bl[nt]);
                    }
                }
            }

            // ---- epilogue ----
            const float* xb = x + ((size_t)b * TSTEPS + t) * NNPOS;
            #pragma unroll
            for (int mt = 0; mt < 2; mt++) {
                #pragma unroll
                for (int rh = 0; rh < 2; rh++) {
                    const int prow = wm * 32 + mt * 16 + g + rh * 8;
                    const int pos  = p0 + prow;
                    const float xm1 = (pos >= 1) ? xb[pos - 1] : 0.f;
                    const float x0v = xb[pos];
                    const float xp1 = (pos <= NNPOS - 2) ? xb[pos + 1] : 0.f;
                    const int chl = wn * 8 + 2 * tq;
                    const size_t base = ((size_t)b * NNPOS + pos) * 64 + hs * 32 + chl;
                    float2 cold = *(const float2*)(g_c + base);
                    float cc[2], hh[2];
                    #pragma unroll
                    for (int lsb = 0; lsb < 2; lsb++) {
                        const int nb = wn * 32 + 2 * tq + lsb;
                        float vi = C[mt][0][rh * 2 + lsb] + bss[nb]      + wxs[nb * 3]        * xm1 + wxs[nb * 3 + 1]        * x0v + wxs[nb * 3 + 2]        * xp1;
                        float vf = C[mt][1][rh * 2 + lsb] + bss[nb + 8]  + wxs[(nb + 8) * 3]  * xm1 + wxs[(nb + 8) * 3 + 1]  * x0v + wxs[(nb + 8) * 3 + 2]  * xp1;
                        float vo = C[mt][2][rh * 2 + lsb] + bss[nb + 16] + wxs[(nb + 16) * 3] * xm1 + wxs[(nb + 16) * 3 + 1] * x0v + wxs[(nb + 16) * 3 + 2] * xp1;
                        float vg = C[mt][3][rh * 2 + lsb] + bss[nb + 24] + wxs[(nb + 24) * 3] * xm1 + wxs[(nb + 24) * 3 + 1] * x0v + wxs[(nb + 24) * 3 + 2] * xp1;
                        float co = lsb ? cold.y : cold.x;
                        float c2 = sigm(vf) * co + sigm(vi) * tanhq(vg);
                        cc[lsb] = c2;
                        hh[lsb] = sigm(vo) * tanhq(c2);
                    }
                    *(float2*)(g_c + base) = make_float2(cc[0], cc[1]);
                    __nv_bfloat162 vhi, vlo;
                    vhi.x = __float2bfloat16(hh[0]);
                    vhi.y = __float2bfloat16(hh[1]);
                    vlo.x = __float2bfloat16(hh[0] - __bfloat162float(vhi.x));
                    vlo.y = __float2bfloat16(hh[1] - __bfloat162float(vhi.y));
                    *(__nv_bfloat162*)&g_hp[wr][0][base] = vhi;
                    *(__nv_bfloat162*)&g_hp[wr][1][base] = vlo;
                }
            }

            if (i < 7) {
                asm volatile("cp.async.wait_group 0;" ::: "memory");
                __syncthreads();
                buf ^= 1;
            }
        }

        if (t < TSTEPS - 1) grid_barrier();
    }
}

// ---- final 1x1 conv + broadcast over TS (final h in buf 0) ----
__global__ void __launch_bounds__(256)
fc_kernel(const float* __restrict__ fc_w, const float* __restrict__ fc_b,
          float* __restrict__ out) {
    __shared__ float w_s[HIDDEN];
    int tid = threadIdx.x;
    if (tid < HIDDEN) w_s[tid] = fc_w[tid];
    __syncthreads();

    int b = blockIdx.y;
    int n = blockIdx.x * 256 + tid;
    const __nv_bfloat16* hhi = &g_hp[0][0][((size_t)b * NNPOS + n) * 64];
    const __nv_bfloat16* hlo = &g_hp[0][1][((size_t)b * NNPOS + n) * 64];
    float acc = fc_b[0];
    #pragma unroll
    for (int ch = 0; ch < HIDDEN; ch++)
        acc += (__bfloat162float(hhi[ch]) + __bfloat162float(hlo[ch])) * w_s[ch];

    #pragma unroll
    for (int t = 0; t < TSTEPS; t++)
        out[((size_t)b * TSTEPS + t) * NNPOS + n] = acc;
}

extern "C" void kernel_launch(void* const* d_in, const int* in_sizes, int n_in,
                              void* d_out, int out_size) {
    const float* x      = (const float*)d_in[0];  // [16,16,4096,1]
    const float* conv_w = (const float*)d_in[1];  // [256,65,3,3]
    const float* conv_b = (const float*)d_in[2];  // [256]
    const float* fc_w   = (const float*)d_in[3];  // [1,64,1,1]
    const float* fc_b   = (const float*)d_in[4];  // [1]
    float* out = (float*)d_out;                   // [16,16,4096,1]

    cudaFuncSetAttribute(lstm_persist, cudaFuncAttributeMaxDynamicSharedMemorySize, SMEM_BYTES);

    repack_img<<<(2 * 128 * 192 + 255) / 256, 256>>>(conv_w);
    zero_state<<<1024, 256>>>();

    lstm_persist<<<dim3(64, 2), NTHREADS, SMEM_BYTES>>>(x, conv_w, conv_b);

    fc_kernel<<<dim3(NNPOS / 256, BATCH), 256>>>(fc_w, fc_b, out);
}

// round 14
// speedup vs baseline: 1.0879x; 1.0175x over previous
#include <cuda_runtime.h>
#include <cuda_bf16.h>
#include <math.h>

#define HIDDEN 64
#define BATCH  16
#define TSTEPS 16
#define NNPOS  4096
#define TILE_P 128
#define NTHREADS 256
#define GROUP_CTAS 16            // CTAs per batch group

typedef unsigned int u32;

// ---- smem layout (bytes) ----
#define A_STRIDE 144                 // 64 bf16 = 128B padded to 144 (conflict-free)
#define B_STRIDE 400                 // 192 bf16 = 384B padded to 400
#define APLANE2  (130 * A_STRIDE)    // 18720 (one plane, 130 rows)
#define ABUF     (2 * APLANE2)       // 37440 (hi+lo planes, single buffer)
#define BPLANE   (64 * B_STRIDE)     // 25600 (64 n-rows per CTA)
#define OFF_A    0
#define OFF_B    ABUF                // 37440; 2 planes
#define OFF_WX   (OFF_B + 2 * BPLANE)   // 88640; 128*3 floats
#define OFF_BIAS (OFF_WX + 1536)        // 90176; 128 floats
#define SMEM_BYTES (OFF_BIAS + 512)     // 90688  -> 2 CTAs/SM

// ---- persistent scratch ----
__device__ __align__(16) __nv_bfloat16 g_wimg[2 * 2 * 128 * 192];
__device__ __align__(16) __nv_bfloat16 g_hp[2][2][(size_t)BATCH * NNPOS * HIDDEN]; // [buf][plane][(b*NN+p)*64+ch]
__device__ __align__(16) float         g_c[(size_t)BATCH * NNPOS * HIDDEN];
__device__ int          g_cnt[BATCH * 32];      // per-batch barrier, cacheline-spread
__device__ volatile int g_gen[BATCH * 32];

__device__ __forceinline__ float sigm(float v)  { return 1.f / (1.f + __expf(-v)); }
__device__ __forceinline__ float tanhq(float v) { return 1.f - 2.f / (__expf(2.f * v) + 1.f); }

__device__ __forceinline__ u32 smem_u32(const void* p) {
    u32 a; asm("{ .reg .u64 t; cvta.to.shared.u64 t, %1; cvt.u32.u64 %0, t; }" : "=r"(a) : "l"(p));
    return a;
}

__device__ __forceinline__ void mma16816(float* c, const u32* a, const u32* bf) {
    asm volatile(
        "mma.sync.aligned.m16n8k16.row.col.f32.bf16.bf16.f32 "
        "{%0,%1,%2,%3},{%4,%5,%6,%7},{%8,%9},{%0,%1,%2,%3};"
        : "+f"(c[0]), "+f"(c[1]), "+f"(c[2]), "+f"(c[3])
        : "r"(a[0]), "r"(a[1]), "r"(a[2]), "r"(a[3]), "r"(bf[0]), "r"(bf[1]));
}

// prefetch one A tile (2 planes x 130 rows x 8 chunks) via cp.async.cg (L1-bypass)
__device__ __forceinline__ void prefetchA(u32 sbase, int b, int p0, int rd, int tid) {
    for (int m = tid; m < 2080; m += NTHREADS) {
        int pl = m / 1040, r = (m % 1040) / 8, c = m % 8;
        int pos = p0 - 1 + r;
        bool ok = (pos >= 0 && pos < NNPOS);
        int posc = ok ? pos : 0;
        const void* src = (const char*)&g_hp[rd][pl][((size_t)b * NNPOS + posc) * 64] + c * 16;
        u32 dst = sbase + OFF_A + pl * APLANE2 + r * A_STRIDE + c * 16;
        int sz = ok ? 16 : 0;
        asm volatile("cp.async.cg.shared.global [%0], [%1], 16, %2;" :: "r"(dst), "l"(src), "r"(sz));
    }
    asm volatile("cp.async.commit_group;" ::: "memory");
}

__device__ __forceinline__ void group_barrier(int b) {
    __syncthreads();
    if (threadIdx.x == 0) {
        __threadfence();
        int idx = b * 32;
        int gen = g_gen[idx];
        if (atomicAdd(&g_cnt[idx], 1) == GROUP_CTAS - 1) {
            g_cnt[idx] = 0;
            __threadfence();
            g_gen[idx] = gen + 1;
        } else {
            while (g_gen[idx] == gen) { }
        }
        __threadfence();
    }
    __syncthreads();
}

// ---- setup: weight image ----
__global__ void repack_img(const float* __restrict__ conv_w) {
    int idx = blockIdx.x * blockDim.x + threadIdx.x;
    if (idx >= 2 * 128 * 192) return;
    int hs  = idx / 24576;
    int rem = idx % 24576;
    int n = rem / 192, k = rem % 192;
    int gate = (n >> 3) & 3;
    int chl  = (n >> 5) * 8 + (n & 7);
    int oc = gate * 64 + hs * 32 + chl;
    int kh = k / 64, ic = k % 64;
    float w = conv_w[((oc * 65 + (ic + 1)) * 3 + kh) * 3 + 1];
    __nv_bfloat16 whi = __float2bfloat16(w);
    __nv_bfloat16 wlo = __float2bfloat16(w - __bfloat162float(whi));
    g_wimg[((size_t)(hs * 2 + 0) * 128 + n) * 192 + k] = whi;
    g_wimg[((size_t)(hs * 2 + 1) * 128 + n) * 192 + k] = wlo;
}

__global__ void zero_state() {
    size_t i = (size_t)blockIdx.x * blockDim.x + threadIdx.x;
    size_t stride = (size_t)gridDim.x * blockDim.x;
    const size_t nc = (size_t)BATCH * NNPOS * HIDDEN;
    for (size_t j = i; j < nc; j += stride) g_c[j] = 0.f;
    u32* h0 = (u32*)&g_hp[0][0][0];            // both planes of buf0 contiguous
    for (size_t j = i; j < nc; j += stride) h0[j] = 0u;
    if (i < BATCH * 32) { g_cnt[i] = 0; g_gen[i] = 0; }
}

// ---- persistent kernel: 256 CTAs (2/SM), per-batch barriers ----
// blockIdx.y = batch b; blockIdx.x = j (0..15): nq = j>>3, hs = (j>>2)&1, tiles (j&3)*8 + i
__global__ void __launch_bounds__(NTHREADS, 2)
lstm_persist(const float* __restrict__ x, const float* __restrict__ conv_w,
             const float* __restrict__ conv_b) {
    extern __shared__ unsigned char sm[];
    const u32 sbase = smem_u32(sm);
    const int tid = threadIdx.x, wid = tid >> 5, lane = tid & 31;
    const int g = lane >> 2, tq = lane & 3;
    const int b  = blockIdx.y;
    const int j  = blockIdx.x;
    const int nq = j >> 3, hs = (j >> 2) & 1, tband = j & 3;
    const int wm = wid >> 1, wn = wid & 1;
    const int wne = nq * 2 + wn;      // effective n-block 0..3 within hs image

    // ---- stage B once: rows [nq*64, nq*64+64) of hs image; 2 planes x 64 x 24 uint4
    {
        const uint4* src = (const uint4*)(g_wimg + (size_t)hs * 2 * 128 * 192);
        #pragma unroll
        for (int m = tid; m < 2 * 64 * 24; m += NTHREADS) {
            int pl = m / 1536, r = (m % 1536) / 24, c = m % 24;
            *(uint4*)(sm + OFF_B + pl * BPLANE + r * B_STRIDE + c * 16) =
                src[(size_t)pl * 3072 + (nq * 64 + r) * 24 + c];
        }
    }
    // ---- stage bias/wx once (full 128-entry tables of this hs image) ----
    if (tid < 128) {
        int n = tid;
        int gate = (n >> 3) & 3;
        int chl  = (n >> 5) * 8 + (n & 7);
        int oc = gate * 64 + hs * 32 + chl;
        ((float*)(sm + OFF_BIAS))[n] = conv_b[oc];
        #pragma unroll
        for (int kh = 0; kh < 3; kh++)
            ((float*)(sm + OFF_WX))[n * 3 + kh] = conv_w[((oc * 65 + 0) * 3 + kh) * 3 + 1];
    }

    const float* wxs = (const float*)(sm + OFF_WX);
    const float* bss = (const float*)(sm + OFF_BIAS);

    #pragma unroll 1
    for (int t = 0; t < TSTEPS; t++) {
        const int rd = t & 1, wr = rd ^ 1;

        // prefetch item 0 (h[rd] ready: barrier or zero-init)
        prefetchA(sbase, b, (tband * 8) * TILE_P, rd, tid);
        asm volatile("cp.async.wait_group 0;" ::: "memory");
        __syncthreads();

        #pragma unroll 1
        for (int i = 0; i < 8; i++) {
            const int p0 = (tband * 8 + i) * TILE_P;

            // ---- mainloop: warp tile 32x32, fused hi*hi + lo*hi + hi*lo ----
            float C[2][4][4];
            #pragma unroll
            for (int mt = 0; mt < 2; mt++)
                #pragma unroll
                for (int nt = 0; nt < 4; nt++)
                    #pragma unroll
                    for (int r = 0; r < 4; r++) C[mt][nt][r] = 0.f;

            const unsigned char* Arow = sm + OFF_A + (wm * 32 + g) * A_STRIDE + tq * 4;
            const unsigned char* Brow = sm + OFF_B + (wn * 32 + g) * B_STRIDE + tq * 4;

            #pragma unroll 1
            for (int kh = 0; kh < 3; kh++) {
                const unsigned char* Akh = Arow + kh * A_STRIDE;
                const unsigned char* Bkh = Brow + kh * 128;
                #pragma unroll
                for (int kk = 0; kk < 4; kk++) {
                    u32 bh[4][2], bl[4][2];
                    #pragma unroll
                    for (int nt = 0; nt < 4; nt++) {
                        const unsigned char* q = Bkh + nt * (8 * B_STRIDE) + kk * 32;
                        bh[nt][0] = *(const u32*)q;
                        bh[nt][1] = *(const u32*)(q + 16);
                        bl[nt][0] = *(const u32*)(q + BPLANE);
                        bl[nt][1] = *(const u32*)(q + BPLANE + 16);
                    }
                    #pragma unroll
                    for (int mt = 0; mt < 2; mt++) {
                        const unsigned char* p = Akh + mt * (16 * A_STRIDE) + kk * 32;
                        u32 ah[4], al[4];
                        ah[0] = *(const u32*)p;
                        ah[1] = *(const u32*)(p + 8 * A_STRIDE);
                        ah[2] = *(const u32*)(p + 16);
                        ah[3] = *(const u32*)(p + 8 * A_STRIDE + 16);
                        al[0] = *(const u32*)(p + APLANE2);
                        al[1] = *(const u32*)(p + APLANE2 + 8 * A_STRIDE);
                        al[2] = *(const u32*)(p + APLANE2 + 16);
                        al[3] = *(const u32*)(p + APLANE2 + 8 * A_STRIDE + 16);
                        #pragma unroll
                        for (int nt = 0; nt < 4; nt++) mma16816(C[mt][nt], ah, bh[nt]);
                        #pragma unroll
                        for (int nt = 0; nt < 4; nt++) mma16816(C[mt][nt], al, bh[nt]);
                        #pragma unroll
                        for (int nt = 0; nt < 4; nt++) mma16816(C[mt][nt], ah, bl[nt]);
                    }
                }
            }

            // A fully consumed -> overlap next item's prefetch with epilogue
            __syncthreads();
            if (i < 7) prefetchA(sbase, b, p0 + TILE_P, rd, tid);

            // ---- epilogue ----
            const float* xb = x + ((size_t)b * TSTEPS + t) * NNPOS;
            #pragma unroll
            for (int mt = 0; mt < 2; mt++) {
                #pragma unroll
                for (int rh = 0; rh < 2; rh++) {
                    const int prow = wm * 32 + mt * 16 + g + rh * 8;
                    const int pos  = p0 + prow;
                    const float xm1 = (pos >= 1) ? xb[pos - 1] : 0.f;
                    const float x0v = xb[pos];
                    const float xp1 = (pos <= NNPOS - 2) ? xb[pos + 1] : 0.f;
                    const int chl = wne * 8 + 2 * tq;
                    const size_t base = ((size_t)b * NNPOS + pos) * 64 + hs * 32 + chl;
                    float2 cold = *(const float2*)(g_c + base);
                    float cc[2], hh[2];
                    #pragma unroll
                    for (int lsb = 0; lsb < 2; lsb++) {
                        const int nb = wne * 32 + 2 * tq + lsb;
                        float vi = C[mt][0][rh * 2 + lsb] + bss[nb]      + wxs[nb * 3]        * xm1 + wxs[nb * 3 + 1]        * x0v + wxs[nb * 3 + 2]        * xp1;
                        float vf = C[mt][1][rh * 2 + lsb] + bss[nb + 8]  + wxs[(nb + 8) * 3]  * xm1 + wxs[(nb + 8) * 3 + 1]  * x0v + wxs[(nb + 8) * 3 + 2]  * xp1;
                        float vo = C[mt][2][rh * 2 + lsb] + bss[nb + 16] + wxs[(nb + 16) * 3] * xm1 + wxs[(nb + 16) * 3 + 1] * x0v + wxs[(nb + 16) * 3 + 2] * xp1;
                        float vg = C[mt][3][rh * 2 + lsb] + bss[nb + 24] + wxs[(nb + 24) * 3] * xm1 + wxs[(nb + 24) * 3 + 1] * x0v + wxs[(nb + 24) * 3 + 2] * xp1;
                        float co = lsb ? cold.y : cold.x;
                        float c2 = sigm(vf) * co + sigm(vi) * tanhq(vg);
                        cc[lsb] = c2;
                        hh[lsb] = sigm(vo) * tanhq(c2);
                    }
                    *(float2*)(g_c + base) = make_float2(cc[0], cc[1]);
                    __nv_bfloat162 vhi, vlo;
                    vhi.x = __float2bfloat16(hh[0]);
                    vhi.y = __float2bfloat16(hh[1]);
                    vlo.x = __float2bfloat16(hh[0] - __bfloat162float(vhi.x));
                    vlo.y = __float2bfloat16(hh[1] - __bfloat162float(vhi.y));
                    *(__nv_bfloat162*)&g_hp[wr][0][base] = vhi;
                    *(__nv_bfloat162*)&g_hp[wr][1][base] = vlo;
                }
            }

            if (i < 7) {
                asm volatile("cp.async.wait_group 0;" ::: "memory");
                __syncthreads();
            }
        }

        if (t < TSTEPS - 1) group_barrier(b);
    }
}

// ---- final 1x1 conv + broadcast over TS (final h in buf 0) ----
__global__ void __launch_bounds__(256)
fc_kernel(const float* __restrict__ fc_w, const float* __restrict__ fc_b,
          float* __restrict__ out) {
    __shared__ float w_s[HIDDEN];
    int tid = threadIdx.x;
    if (tid < HIDDEN) w_s[tid] = fc_w[tid];
    __syncthreads();

    int b = blockIdx.y;
    int n = blockIdx.x * 256 + tid;
    const __nv_bfloat16* hhi = &g_hp[0][0][((size_t)b * NNPOS + n) * 64];
    const __nv_bfloat16* hlo = &g_hp[0][1][((size_t)b * NNPOS + n) * 64];
    float acc = fc_b[0];
    #pragma unroll
    for (int ch = 0; ch < HIDDEN; ch++)
        acc += (__bfloat162float(hhi[ch]) + __bfloat162float(hlo[ch])) * w_s[ch];

    #pragma unroll
    for (int t = 0; t < TSTEPS; t++)
        out[((size_t)b * TSTEPS + t) * NNPOS + n] = acc;
}

extern "C" void kernel_launch(void* const* d_in, const int* in_sizes, int n_in,
                              void* d_out, int out_size) {
    const float* x      = (const float*)d_in[0];  // [16,16,4096,1]
    const float* conv_w = (const float*)d_in[1];  // [256,65,3,3]
    const float* conv_b = (const float*)d_in[2];  // [256]
    const float* fc_w   = (const float*)d_in[3];  // [1,64,1,1]
    const float* fc_b   = (const float*)d_in[4];  // [1]
    float* out = (float*)d_out;                   // [16,16,4096,1]

    cudaFuncSetAttribute(lstm_persist, cudaFuncAttributeMaxDynamicSharedMemorySize, SMEM_BYTES);

    repack_img<<<(2 * 128 * 192 + 255) / 256, 256>>>(conv_w);
    zero_state<<<1024, 256>>>();

    lstm_persist<<<dim3(GROUP_CTAS, BATCH), NTHREADS, SMEM_BYTES>>>(x, conv_w, conv_b);

    fc_kernel<<<dim3(NNPOS / 256, BATCH), 256>>>(fc_w, fc_b, out);
}

// round 15
// speedup vs baseline: 1.0971x; 1.0085x over previous
#include <cuda_runtime.h>
#include <cuda_bf16.h>
#include <math.h>

#define HIDDEN 64
#define BATCH  16
#define TSTEPS 16
#define NNPOS  4096
#define TILE_P 128
#define NTHREADS 512
#define GROUP_CTAS 8             // CTAs per batch group

typedef unsigned int u32;

// ---- smem layout (bytes) ----
#define A_STRIDE 144                 // 64 bf16 = 128B padded to 144 (conflict-free)
#define B_STRIDE 400                 // 192 bf16 = 384B padded to 400
#define APLANE2  (136 * A_STRIDE)    // 19584: 4 groups x 34 private rows (halo duplicated)
#define ABUF     (2 * APLANE2)       // 39168 (hi+lo planes)
#define OFF_A    0                   // 2 buffers
#define OFF_B    (2 * ABUF)          // 78336
#define BPLANE   (128 * B_STRIDE)    // 51200
#define OFF_WX   (OFF_B + 2 * BPLANE)   // 180736; 128*3 floats
#define OFF_BIAS (OFF_WX + 1536)        // 182272; 128 floats
#define SMEM_BYTES (OFF_BIAS + 512)     // 182784 -> 1 CTA/SM

// ---- persistent scratch ----
__device__ __align__(16) __nv_bfloat16 g_wimg[2 * 2 * 128 * 192];
__device__ __align__(16) __nv_bfloat16 g_hp[2][2][(size_t)BATCH * NNPOS * HIDDEN]; // [buf][plane][(b*NN+p)*64+ch]
__device__ __align__(16) float         g_c[(size_t)BATCH * NNPOS * HIDDEN];
__device__ int          g_cnt[BATCH * 32];
__device__ volatile int g_gen[BATCH * 32];

__device__ __forceinline__ float sigm(float v)  { return 1.f / (1.f + __expf(-v)); }
__device__ __forceinline__ float tanhq(float v) { return 1.f - 2.f / (__expf(2.f * v) + 1.f); }

__device__ __forceinline__ u32 smem_u32(const void* p) {
    u32 a; asm("{ .reg .u64 t; cvta.to.shared.u64 t, %1; cvt.u32.u64 %0, t; }" : "=r"(a) : "l"(p));
    return a;
}

__device__ __forceinline__ void mma16816(float* c, const u32* a, const u32* bf) {
    asm volatile(
        "mma.sync.aligned.m16n8k16.row.col.f32.bf16.bf16.f32 "
        "{%0,%1,%2,%3},{%4,%5,%6,%7},{%8,%9},{%0,%1,%2,%3};"
        : "+f"(c[0]), "+f"(c[1]), "+f"(c[2]), "+f"(c[3])
        : "r"(a[0]), "r"(a[1]), "r"(a[2]), "r"(a[3]), "r"(bf[0]), "r"(bf[1]));
}

__device__ __forceinline__ void bar_grp(int wm) {
    asm volatile("bar.sync %0, 128;" :: "r"(wm + 1) : "memory");
}

// group prefetch: 34 private rows (2 planes x 8 chunks) via cp.async.cg (L2-only)
__device__ __forceinline__ void prefetchA_grp(u32 sbase, int buf, int wm, int b,
                                              int p0, int rd, int gtid) {
    for (int m = gtid; m < 544; m += 128) {
        int pl = m / 272, rr = (m % 272) >> 3, c = m & 7;
        int pos = p0 + wm * 32 - 1 + rr;
        bool ok = (pos >= 0 && pos < NNPOS);
        int posc = ok ? pos : 0;
        const void* src = (const char*)&g_hp[rd][pl][((size_t)b * NNPOS + posc) * 64] + c * 16;
        u32 dst = sbase + OFF_A + buf * ABUF + pl * APLANE2 + (wm * 34 + rr) * A_STRIDE + c * 16;
        int sz = ok ? 16 : 0;
        asm volatile("cp.async.cg.shared.global [%0], [%1], 16, %2;" :: "r"(dst), "l"(src), "r"(sz));
    }
    asm volatile("cp.async.commit_group;" ::: "memory");
}

__device__ __forceinline__ void group_barrier(int b) {
    __syncthreads();
    if (threadIdx.x == 0) {
        __threadfence();
        int idx = b * 32;
        int gen = g_gen[idx];
        if (atomicAdd(&g_cnt[idx], 1) == GROUP_CTAS - 1) {
            g_cnt[idx] = 0;
            __threadfence();
            g_gen[idx] = gen + 1;
        } else {
            while (g_gen[idx] == gen) { }
        }
        __threadfence();
    }
    __syncthreads();
}

// ---- setup: weight image ----
__global__ void repack_img(const float* __restrict__ conv_w) {
    int idx = blockIdx.x * blockDim.x + threadIdx.x;
    if (idx >= 2 * 128 * 192) return;
    int hs  = idx / 24576;
    int rem = idx % 24576;
    int n = rem / 192, k = rem % 192;
    int gate = (n >> 3) & 3;
    int chl  = (n >> 5) * 8 + (n & 7);
    int oc = gate * 64 + hs * 32 + chl;
    int kh = k / 64, ic = k % 64;
    float w = conv_w[((oc * 65 + (ic + 1)) * 3 + kh) * 3 + 1];
    __nv_bfloat16 whi = __float2bfloat16(w);
    __nv_bfloat16 wlo = __float2bfloat16(w - __bfloat162float(whi));
    g_wimg[((size_t)(hs * 2 + 0) * 128 + n) * 192 + k] = whi;
    g_wimg[((size_t)(hs * 2 + 1) * 128 + n) * 192 + k] = wlo;
}

__global__ void zero_state() {
    size_t i = (size_t)blockIdx.x * blockDim.x + threadIdx.x;
    size_t stride = (size_t)gridDim.x * blockDim.x;
    const size_t nc = (size_t)BATCH * NNPOS * HIDDEN;
    for (size_t j = i; j < nc; j += stride) g_c[j] = 0.f;
    u32* h0 = (u32*)&g_hp[0][0][0];            // both planes of buf0 contiguous
    for (size_t j = i; j < nc; j += stride) h0[j] = 0u;
    if (i < BATCH * 32) { g_cnt[i] = 0; g_gen[i] = 0; }
}

// ---- persistent kernel: 128 CTAs (1/SM), free-running 4-warp groups ----
// blockIdx.y = batch; blockIdx.x = j: hs = j>>2, tband = j&3, items i=0..7 -> tile tband*8+i
__global__ void __launch_bounds__(NTHREADS, 1)
lstm_persist(const float* __restrict__ x, const float* __restrict__ conv_w,
             const float* __restrict__ conv_b) {
    extern __shared__ unsigned char sm[];
    const u32 sbase = smem_u32(sm);
    const int tid = threadIdx.x, wid = tid >> 5, lane = tid & 31;
    const int g = lane >> 2, tq = lane & 3;
    const int b  = blockIdx.y;
    const int j  = blockIdx.x;
    const int hs = j >> 2, tband = j & 3;
    const int wm = wid >> 2, wn = wid & 3;
    const int gtid = tid & 127;

    // ---- stage B once: 2 planes x 128 rows x 24 uint4 ----
    {
        const uint4* src = (const uint4*)(g_wimg + (size_t)hs * 2 * 128 * 192);
        #pragma unroll
        for (int m = tid; m < 2 * 128 * 24; m += NTHREADS) {
            int pl = m / 3072, r = (m % 3072) / 24, c = m % 24;
            *(uint4*)(sm + OFF_B + pl * BPLANE + r * B_STRIDE + c * 16) = src[m];
        }
    }
    // ---- stage bias/wx once ----
    if (tid < 128) {
        int n = tid;
        int gate = (n >> 3) & 3;
        int chl  = (n >> 5) * 8 + (n & 7);
        int oc = gate * 64 + hs * 32 + chl;
        ((float*)(sm + OFF_BIAS))[n] = conv_b[oc];
        #pragma unroll
        for (int kh = 0; kh < 3; kh++)
            ((float*)(sm + OFF_WX))[n * 3 + kh] = conv_w[((oc * 65 + 0) * 3 + kh) * 3 + 1];
    }
    __syncthreads();

    const float* wxs = (const float*)(sm + OFF_WX);
    const float* bss = (const float*)(sm + OFF_BIAS);

    #pragma unroll 1
    for (int t = 0; t < TSTEPS; t++) {
        const int rd = t & 1, wr = rd ^ 1;

        // group-scoped pipeline over 8 items; NO CTA-wide syncs inside
        prefetchA_grp(sbase, 0, wm, b, (tband * 8) * TILE_P, rd, gtid);

        #pragma unroll 1
        for (int i = 0; i < 8; i++) {
            const int p0 = (tband * 8 + i) * TILE_P;
            const int buf = i & 1;

            asm volatile("cp.async.wait_group 0;" ::: "memory");
            bar_grp(wm);          // group's A(i) fully in smem

            // ---- mainloop: warp tile 32x32, fused hi*hi + lo*hi + hi*lo ----
            float C[2][4][4];
            #pragma unroll
            for (int mt = 0; mt < 2; mt++)
                #pragma unroll
                for (int nt = 0; nt < 4; nt++)
                    #pragma unroll
                    for (int r = 0; r < 4; r++) C[mt][nt][r] = 0.f;

            // group-private A slab: local row rr = mt*16 + g + rh*8 + kh  (pos = p0+wm*32-1+rr)
            const unsigned char* Arow = sm + OFF_A + buf * ABUF + (wm * 34 + g) * A_STRIDE + tq * 4;
            const unsigned char* Brow = sm + OFF_B + (wn * 32 + g) * B_STRIDE + tq * 4;

            #pragma unroll 1
            for (int kh = 0; kh < 3; kh++) {
                const unsigned char* Akh = Arow + kh * A_STRIDE;
                const unsigned char* Bkh = Brow + kh * 128;
                #pragma unroll
                for (int kk = 0; kk < 4; kk++) {
                    u32 bh[4][2], bl[4][2];
                    #pragma unroll
                    for (int nt = 0; nt < 4; nt++) {
                        const unsigned char* q = Bkh + nt * (8 * B_STRIDE) + kk * 32;
                        bh[nt][0] = *(const u32*)q;
                        bh[nt][1] = *(const u32*)(q + 16);
                        bl[nt][0] = *(const u32*)(q + BPLANE);
                        bl[nt][1] = *(const u32*)(q + BPLANE + 16);
                    }
                    #pragma unroll
                    for (int mt = 0; mt < 2; mt++) {
                        const unsigned char* p = Akh + mt * (16 * A_STRIDE) + kk * 32;
                        u32 ah[4], al[4];
                        ah[0] = *(const u32*)p;
                        ah[1] = *(const u32*)(p + 8 * A_STRIDE);
                        ah[2] = *(const u32*)(p + 16);
                        ah[3] = *(const u32*)(p + 8 * A_STRIDE + 16);
                        al[0] = *(const u32*)(p + APLANE2);
                        al[1] = *(const u32*)(p + APLANE2 + 8 * A_STRIDE);
                        al[2] = *(const u32*)(p + APLANE2 + 16);
                        al[3] = *(const u32*)(p + APLANE2 + 8 * A_STRIDE + 16);
                        #pragma unroll
                        for (int nt = 0; nt < 4; nt++) mma16816(C[mt][nt], ah, bh[nt]);
                        #pragma unroll
                        for (int nt = 0; nt < 4; nt++) mma16816(C[mt][nt], al, bh[nt]);
                        #pragma unroll
                        for (int nt = 0; nt < 4; nt++) mma16816(C[mt][nt], ah, bl[nt]);
                    }
                }
            }

            bar_grp(wm);          // group done reading buf -> safe to prefetch into other buf
            if (i < 7)
                prefetchA_grp(sbase, buf ^ 1, wm, b, p0 + TILE_P, rd, gtid);

            // ---- epilogue (overlaps this group's prefetch & other groups' mainloops) ----
            const float* xb = x + ((size_t)b * TSTEPS + t) * NNPOS;
            #pragma unroll
            for (int mt = 0; mt < 2; mt++) {
                #pragma unroll
                for (int rh = 0; rh < 2; rh++) {
                    const int prow = wm * 32 + mt * 16 + g + rh * 8;
                    const int pos  = p0 + prow;
                    const float xm1 = (pos >= 1) ? xb[pos - 1] : 0.f;
                    const float x0v = xb[pos];
                    const float xp1 = (pos <= NNPOS - 2) ? xb[pos + 1] : 0.f;
                    const int chl = wn * 8 + 2 * tq;
                    const size_t base = ((size_t)b * NNPOS + pos) * 64 + hs * 32 + chl;
                    float2 cold = *(const float2*)(g_c + base);
                    float cc[2], hh[2];
                    #pragma unroll
                    for (int lsb = 0; lsb < 2; lsb++) {
                        const int nb = wn * 32 + 2 * tq + lsb;
                        float vi = C[mt][0][rh * 2 + lsb] + bss[nb]      + wxs[nb * 3]        * xm1 + wxs[nb * 3 + 1]        * x0v + wxs[nb * 3 + 2]        * xp1;
                        float vf = C[mt][1][rh * 2 + lsb] + bss[nb + 8]  + wxs[(nb + 8) * 3]  * xm1 + wxs[(nb + 8) * 3 + 1]  * x0v + wxs[(nb + 8) * 3 + 2]  * xp1;
                        float vo = C[mt][2][rh * 2 + lsb] + bss[nb + 16] + wxs[(nb + 16) * 3] * xm1 + wxs[(nb + 16) * 3 + 1] * x0v + wxs[(nb + 16) * 3 + 2] * xp1;
                        float vg = C[mt][3][rh * 2 + lsb] + bss[nb + 24] + wxs[(nb + 24) * 3] * xm1 + wxs[(nb + 24) * 3 + 1] * x0v + wxs[(nb + 24) * 3 + 2] * xp1;
                        float co = lsb ? cold.y : cold.x;
                        float c2 = sigm(vf) * co + sigm(vi) * tanhq(vg);
                        cc[lsb] = c2;
                        hh[lsb] = sigm(vo) * tanhq(c2);
                    }
                    *(float2*)(g_c + base) = make_float2(cc[0], cc[1]);
                    __nv_bfloat162 vhi, vlo;
                    vhi.x = __float2bfloat16(hh[0]);
                    vhi.y = __float2bfloat16(hh[1]);
                    vlo.x = __float2bfloat16(hh[0] - __bfloat162float(vhi.x));
                    vlo.y = __float2bfloat16(hh[1] - __bfloat162float(vhi.y));
                    *(__nv_bfloat162*)&g_hp[wr][0][base] = vhi;
                    *(__nv_bfloat162*)&g_hp[wr][1][base] = vlo;
                }
            }
        }

        if (t < TSTEPS - 1) group_barrier(b);
    }
}

// ---- final 1x1 conv + broadcast over TS (final h in buf 0) ----
__global__ void __launch_bounds__(256)
fc_kernel(const float* __restrict__ fc_w, const float* __restrict__ fc_b,
          float* __restrict__ out) {
    __shared__ float w_s[HIDDEN];
    int tid = threadIdx.x;
    if (tid < HIDDEN) w_s[tid] = fc_w[tid];
    __syncthreads();

    int b = blockIdx.y;
    int n = blockIdx.x * 256 + tid;
    const __nv_bfloat16* hhi = &g_hp[0][0][((size_t)b * NNPOS + n) * 64];
    const __nv_bfloat16* hlo = &g_hp[0][1][((size_t)b * NNPOS + n) * 64];
    float acc = fc_b[0];
    #pragma unroll
    for (int ch = 0; ch < HIDDEN; ch++)
        acc += (__bfloat162float(hhi[ch]) + __bfloat162float(hlo[ch])) * w_s[ch];

    #pragma unroll
    for (int t = 0; t < TSTEPS; t++)
        out[((size_t)b * TSTEPS + t) * NNPOS + n] = acc;
}

extern "C" void kernel_launch(void* const* d_in, const int* in_sizes, int n_in,
                              void* d_out, int out_size) {
    const float* x      = (const float*)d_in[0];  // [16,16,4096,1]
    const float* conv_w = (const float*)d_in[1];  // [256,65,3,3]
    const float* conv_b = (const float*)d_in[2];  // [256]
    const float* fc_w   = (const float*)d_in[3];  // [1,64,1,1]
    const float* fc_b   = (const float*)d_in[4];  // [1]
    float* out = (float*)d_out;                   // [16,16,4096,1]

    cudaFuncSetAttribute(lstm_persist, cudaFuncAttributeMaxDynamicSharedMemorySize, SMEM_BYTES);

    repack_img<<<(2 * 128 * 192 + 255) / 256, 256>>>(conv_w);
    zero_state<<<1024, 256>>>();

    lstm_persist<<<dim3(GROUP_CTAS, BATCH), NTHREADS, SMEM_BYTES>>>(x, conv_w, conv_b);

    fc_kernel<<<dim3(NNPOS / 256, BATCH), 256>>>(fc_w, fc_b, out);
}

// round 16
// speedup vs baseline: 1.2046x; 1.0979x over previous
#include <cuda_runtime.h>
#include <cuda_bf16.h>
#include <math.h>

#define HIDDEN 64
#define BATCH  16
#define TSTEPS 16
#define NNPOS  4096
#define TILE_P 128
#define NTHREADS 512
#define GROUP_CTAS 8             // CTAs per batch group

typedef unsigned int u32;

// ---- smem layout (bytes) ----
#define A_STRIDE 144                 // 64 bf16 = 128B padded to 144 (conflict-free)
#define B_STRIDE 400                 // 192 bf16 = 384B padded to 400
#define APLANE2  (136 * A_STRIDE)    // 19584: 4 groups x 34 private rows (halo duplicated)
#define ABUF     (2 * APLANE2)       // 39168 (hi+lo planes)
#define OFF_A    0                   // 2 buffers
#define OFF_B    (2 * ABUF)          // 78336
#define BPLANE   (128 * B_STRIDE)    // 51200
#define OFF_WX   (OFF_B + 2 * BPLANE)   // 180736; 128*3 floats
#define OFF_BIAS (OFF_WX + 1536)        // 182272; 128 floats
#define SMEM_BYTES (OFF_BIAS + 512)     // 182784 -> 1 CTA/SM

// ---- persistent scratch ----
__device__ __align__(16) __nv_bfloat16 g_wimg[2 * 2 * 128 * 192];
__device__ __align__(16) __nv_bfloat16 g_hp[2][2][(size_t)BATCH * NNPOS * HIDDEN]; // [buf][plane][(b*NN+p)*64+ch]
__device__ __align__(16) float         g_c[(size_t)BATCH * NNPOS * HIDDEN];
__device__ int          g_cnt[BATCH * 32];
__device__ volatile int g_gen[BATCH * 32];

__device__ __forceinline__ u32 smem_u32(const void* p) {
    u32 a; asm("{ .reg .u64 t; cvta.to.shared.u64 t, %1; cvt.u32.u64 %0, t; }" : "=r"(a) : "l"(p));
    return a;
}

__device__ __forceinline__ float frcp(float x) {
    float r; asm("rcp.approx.f32 %0, %1;" : "=f"(r) : "f"(x)); return r;
}

// Eigen-style rational tanh: returns numerator and denominator (FMA-only).
// tanh(x) ~= (x*P(x^2)) / Q(x^2), |x| clamped to 7.99881172; accuracy ~1e-6.
__device__ __forceinline__ void tanh_nd(float x, float& n, float& d) {
    x = fminf(fmaxf(x, -7.99881172f), 7.99881172f);
    float x2 = x * x;
    float p = -2.76076847742355e-16f;
    p = fmaf(p, x2, 2.00018790482477e-13f);
    p = fmaf(p, x2, -8.60467152213735e-11f);
    p = fmaf(p, x2, 5.12229709037114e-08f);
    p = fmaf(p, x2, 1.48572235717979e-05f);
    p = fmaf(p, x2, 6.37261928875436e-04f);
    p = fmaf(p, x2, 4.89352455891786e-03f);
    n = x * p;
    float q = 1.19825839466702e-06f;
    q = fmaf(q, x2, 1.18534705686654e-04f);
    q = fmaf(q, x2, 2.26843463243900e-03f);
    q = fmaf(q, x2, 4.89352518554385e-03f);
    d = q;
}

// 8 reciprocals with ONE rcp.approx (product tree); dens in [0.0049, ~1].
__device__ __forceinline__ void rcp8(const float* d, float* inv) {
    float q01 = d[0] * d[1], q23 = d[2] * d[3], q45 = d[4] * d[5], q67 = d[6] * d[7];
    float q0123 = q01 * q23, q4567 = q45 * q67;
    float r = frcp(q0123 * q4567);
    float r0123 = r * q4567, r4567 = r * q0123;
    float r01 = r0123 * q23, r23 = r0123 * q01, r45 = r4567 * q67, r67 = r4567 * q45;
    inv[0] = r01 * d[1]; inv[1] = r01 * d[0];
    inv[2] = r23 * d[3]; inv[3] = r23 * d[2];
    inv[4] = r45 * d[5]; inv[5] = r45 * d[4];
    inv[6] = r67 * d[7]; inv[7] = r67 * d[6];
}

__device__ __forceinline__ void mma16816(float* c, const u32* a, const u32* bf) {
    asm volatile(
        "mma.sync.aligned.m16n8k16.row.col.f32.bf16.bf16.f32 "
        "{%0,%1,%2,%3},{%4,%5,%6,%7},{%8,%9},{%0,%1,%2,%3};"
        : "+f"(c[0]), "+f"(c[1]), "+f"(c[2]), "+f"(c[3])
        : "r"(a[0]), "r"(a[1]), "r"(a[2]), "r"(a[3]), "r"(bf[0]), "r"(bf[1]));
}

__device__ __forceinline__ void bar_grp(int wm) {
    asm volatile("bar.sync %0, 128;" :: "r"(wm + 1) : "memory");
}

// group prefetch: 34 private rows (2 planes x 8 chunks) via cp.async.cg (L2-only)
__device__ __forceinline__ void prefetchA_grp(u32 sbase, int buf, int wm, int b,
                                              int p0, int rd, int gtid) {
    for (int m = gtid; m < 544; m += 128) {
        int pl = m / 272, rr = (m % 272) >> 3, c = m & 7;
        int pos = p0 + wm * 32 - 1 + rr;
        bool ok = (pos >= 0 && pos < NNPOS);
        int posc = ok ? pos : 0;
        const void* src = (const char*)&g_hp[rd][pl][((size_t)b * NNPOS + posc) * 64] + c * 16;
        u32 dst = sbase + OFF_A + buf * ABUF + pl * APLANE2 + (wm * 34 + rr) * A_STRIDE + c * 16;
        int sz = ok ? 16 : 0;
        asm volatile("cp.async.cg.shared.global [%0], [%1], 16, %2;" :: "r"(dst), "l"(src), "r"(sz));
    }
    asm volatile("cp.async.commit_group;" ::: "memory");
}

__device__ __forceinline__ void group_barrier(int b) {
    __syncthreads();
    if (threadIdx.x == 0) {
        __threadfence();
        int idx = b * 32;
        int gen = g_gen[idx];
        if (atomicAdd(&g_cnt[idx], 1) == GROUP_CTAS - 1) {
            g_cnt[idx] = 0;
            __threadfence();
            g_gen[idx] = gen + 1;
        } else {
            while (g_gen[idx] == gen) { }
        }
        __threadfence();
    }
    __syncthreads();
}

// ---- setup: weight image ----
__global__ void repack_img(const float* __restrict__ conv_w) {
    int idx = blockIdx.x * blockDim.x + threadIdx.x;
    if (idx >= 2 * 128 * 192) return;
    int hs  = idx / 24576;
    int rem = idx % 24576;
    int n = rem / 192, k = rem % 192;
    int gate = (n >> 3) & 3;
    int chl  = (n >> 5) * 8 + (n & 7);
    int oc = gate * 64 + hs * 32 + chl;
    int kh = k / 64, ic = k % 64;
    float w = conv_w[((oc * 65 + (ic + 1)) * 3 + kh) * 3 + 1];
    __nv_bfloat16 whi = __float2bfloat16(w);
    __nv_bfloat16 wlo = __float2bfloat16(w - __bfloat162float(whi));
    g_wimg[((size_t)(hs * 2 + 0) * 128 + n) * 192 + k] = whi;
    g_wimg[((size_t)(hs * 2 + 1) * 128 + n) * 192 + k] = wlo;
}

__global__ void zero_state() {
    size_t i = (size_t)blockIdx.x * blockDim.x + threadIdx.x;
    size_t stride = (size_t)gridDim.x * blockDim.x;
    const size_t nc = (size_t)BATCH * NNPOS * HIDDEN;
    for (size_t j = i; j < nc; j += stride) g_c[j] = 0.f;
    u32* h0 = (u32*)&g_hp[0][0][0];            // both planes of buf0 contiguous
    for (size_t j = i; j < nc; j += stride) h0[j] = 0u;
    if (i < BATCH * 32) { g_cnt[i] = 0; g_gen[i] = 0; }
}

// ---- persistent kernel: 128 CTAs (1/SM), free-running 4-warp groups ----
__global__ void __launch_bounds__(NTHREADS, 1)
lstm_persist(const float* __restrict__ x, const float* __restrict__ conv_w,
             const float* __restrict__ conv_b) {
    extern __shared__ unsigned char sm[];
    const u32 sbase = smem_u32(sm);
    const int tid = threadIdx.x, wid = tid >> 5, lane = tid & 31;
    const int g = lane >> 2, tq = lane & 3;
    const int b  = blockIdx.y;
    const int j  = blockIdx.x;
    const int hs = j >> 2, tband = j & 3;
    const int wm = wid >> 2, wn = wid & 3;
    const int gtid = tid & 127;

    // ---- stage B once ----
    {
        const uint4* src = (const uint4*)(g_wimg + (size_t)hs * 2 * 128 * 192);
        #pragma unroll
        for (int m = tid; m < 2 * 128 * 24; m += NTHREADS) {
            int pl = m / 3072, r = (m % 3072) / 24, c = m % 24;
            *(uint4*)(sm + OFF_B + pl * BPLANE + r * B_STRIDE + c * 16) = src[m];
        }
    }
    // ---- stage bias/wx once ----
    if (tid < 128) {
        int n = tid;
        int gate = (n >> 3) & 3;
        int chl  = (n >> 5) * 8 + (n & 7);
        int oc = gate * 64 + hs * 32 + chl;
        ((float*)(sm + OFF_BIAS))[n] = conv_b[oc];
        #pragma unroll
        for (int kh = 0; kh < 3; kh++)
            ((float*)(sm + OFF_WX))[n * 3 + kh] = conv_w[((oc * 65 + 0) * 3 + kh) * 3 + 1];
    }
    __syncthreads();

    const float* wxs = (const float*)(sm + OFF_WX);
    const float* bss = (const float*)(sm + OFF_BIAS);

    #pragma unroll 1
    for (int t = 0; t < TSTEPS; t++) {
        const int rd = t & 1, wr = rd ^ 1;

        prefetchA_grp(sbase, 0, wm, b, (tband * 8) * TILE_P, rd, gtid);

        #pragma unroll 1
        for (int i = 0; i < 8; i++) {
            const int p0 = (tband * 8 + i) * TILE_P;
            const int buf = i & 1;

            asm volatile("cp.async.wait_group 0;" ::: "memory");
            bar_grp(wm);

            // ---- mainloop: warp tile 32x32, fused hi*hi + lo*hi + hi*lo ----
            float C[2][4][4];
            #pragma unroll
            for (int mt = 0; mt < 2; mt++)
                #pragma unroll
                for (int nt = 0; nt < 4; nt++)
                    #pragma unroll
                    for (int r = 0; r < 4; r++) C[mt][nt][r] = 0.f;

            const unsigned char* Arow = sm + OFF_A + buf * ABUF + (wm * 34 + g) * A_STRIDE + tq * 4;
            const unsigned char* Brow = sm + OFF_B + (wn * 32 + g) * B_STRIDE + tq * 4;

            #pragma unroll 1
            for (int kh = 0; kh < 3; kh++) {
                const unsigned char* Akh = Arow + kh * A_STRIDE;
                const unsigned char* Bkh = Brow + kh * 128;
                #pragma unroll
                for (int kk = 0; kk < 4; kk++) {
                    u32 bh[4][2], bl[4][2];
                    #pragma unroll
                    for (int nt = 0; nt < 4; nt++) {
                        const unsigned char* q = Bkh + nt * (8 * B_STRIDE) + kk * 32;
                        bh[nt][0] = *(const u32*)q;
                        bh[nt][1] = *(const u32*)(q + 16);
                        bl[nt][0] = *(const u32*)(q + BPLANE);
                        bl[nt][1] = *(const u32*)(q + BPLANE + 16);
                    }
                    #pragma unroll
                    for (int mt = 0; mt < 2; mt++) {
                        const unsigned char* p = Akh + mt * (16 * A_STRIDE) + kk * 32;
                        u32 ah[4], al[4];
                        ah[0] = *(const u32*)p;
                        ah[1] = *(const u32*)(p + 8 * A_STRIDE);
                        ah[2] = *(const u32*)(p + 16);
                        ah[3] = *(const u32*)(p + 8 * A_STRIDE + 16);
                        al[0] = *(const u32*)(p + APLANE2);
                        al[1] = *(const u32*)(p + APLANE2 + 8 * A_STRIDE);
                        al[2] = *(const u32*)(p + APLANE2 + 16);
                        al[3] = *(const u32*)(p + APLANE2 + 8 * A_STRIDE + 16);
                        #pragma unroll
                        for (int nt = 0; nt < 4; nt++) mma16816(C[mt][nt], ah, bh[nt]);
                        #pragma unroll
                        for (int nt = 0; nt < 4; nt++) mma16816(C[mt][nt], al, bh[nt]);
                        #pragma unroll
                        for (int nt = 0; nt < 4; nt++) mma16816(C[mt][nt], ah, bl[nt]);
                    }
                }
            }

            bar_grp(wm);
            if (i < 7)
                prefetchA_grp(sbase, buf ^ 1, wm, b, p0 + TILE_P, rd, gtid);

            // ---- epilogue: MUFU-free gates (rational tanh + batched rcp) ----
            const float* xb = x + ((size_t)b * TSTEPS + t) * NNPOS;
            #pragma unroll
            for (int mt = 0; mt < 2; mt++) {
                #pragma unroll
                for (int rh = 0; rh < 2; rh++) {
                    const int prow = wm * 32 + mt * 16 + g + rh * 8;
                    const int pos  = p0 + prow;
                    const float xm1 = (pos >= 1) ? xb[pos - 1] : 0.f;
                    const float x0v = xb[pos];
                    const float xp1 = (pos <= NNPOS - 2) ? xb[pos + 1] : 0.f;
                    const int chl = wn * 8 + 2 * tq;
                    const size_t base = ((size_t)b * NNPOS + pos) * 64 + hs * 32 + chl;
                    float2 cold = *(const float2*)(g_c + base);

                    // gate preactivations for both lsb cells
                    float vv[2][4];
                    #pragma unroll
                    for (int lsb = 0; lsb < 2; lsb++) {
                        const int nb = vv[0][0] == vv[0][0] ? wn * 32 + 2 * tq + lsb : 0; // keep idx simple
                        const int nbb = wn * 32 + 2 * tq + lsb;
                        #pragma unroll
                        for (int gate = 0; gate < 4; gate++) {
                            const int ni = nbb + gate * 8;
                            vv[lsb][gate] = C[mt][gate][rh * 2 + lsb] + bss[ni]
                                          + wxs[ni * 3] * xm1 + wxs[ni * 3 + 1] * x0v
                                          + wxs[ni * 3 + 2] * xp1;
                        }
                        (void)nb;
                    }

                    // phase 1: 8 rational tanh (i,f,o use v/2; g uses v), one rcp
                    float nn[8], dd[8], inv[8];
                    #pragma unroll
                    for (int lsb = 0; lsb < 2; lsb++) {
                        tanh_nd(0.5f * vv[lsb][0], nn[lsb * 4 + 0], dd[lsb * 4 + 0]);
                        tanh_nd(0.5f * vv[lsb][1], nn[lsb * 4 + 1], dd[lsb * 4 + 1]);
                        tanh_nd(0.5f * vv[lsb][2], nn[lsb * 4 + 2], dd[lsb * 4 + 2]);
                        tanh_nd(vv[lsb][3],        nn[lsb * 4 + 3], dd[lsb * 4 + 3]);
                    }
                    rcp8(dd, inv);

                    float cc[2], so[2];
                    #pragma unroll
                    for (int lsb = 0; lsb < 2; lsb++) {
                        float si = fmaf(nn[lsb * 4 + 0] * inv[lsb * 4 + 0], 0.5f, 0.5f);
                        float sf = fmaf(nn[lsb * 4 + 1] * inv[lsb * 4 + 1], 0.5f, 0.5f);
                        so[lsb]  = fmaf(nn[lsb * 4 + 2] * inv[lsb * 4 + 2], 0.5f, 0.5f);
                        float tg = nn[lsb * 4 + 3] * inv[lsb * 4 + 3];
                        float co = lsb ? cold.y : cold.x;
                        cc[lsb] = sf * co + si * tg;
                    }

                    // phase 2: tanh(c2) for both cells, one rcp
                    float nc0, dc0, nc1, dc1;
                    tanh_nd(cc[0], nc0, dc0);
                    tanh_nd(cc[1], nc1, dc1);
                    float rr = frcp(dc0 * dc1);
                    float h0 = so[0] * (nc0 * (dc1 * rr));
                    float h1 = so[1] * (nc1 * (dc0 * rr));

                    *(float2*)(g_c + base) = make_float2(cc[0], cc[1]);
                    __nv_bfloat162 vhi, vlo;
                    vhi.x = __float2bfloat16(h0);
                    vhi.y = __float2bfloat16(h1);
                    vlo.x = __float2bfloat16(h0 - __bfloat162float(vhi.x));
                    vlo.y = __float2bfloat16(h1 - __bfloat162float(vhi.y));
                    *(__nv_bfloat162*)&g_hp[wr][0][base] = vhi;
                    *(__nv_bfloat162*)&g_hp[wr][1][base] = vlo;
                }
            }
        }

        if (t < TSTEPS - 1) group_barrier(b);
    }
}

// ---- final 1x1 conv + broadcast over TS (final h in buf 0) ----
__global__ void __launch_bounds__(256)
fc_kernel(const float* __restrict__ fc_w, const float* __restrict__ fc_b,
          float* __restrict__ out) {
    __shared__ float w_s[HIDDEN];
    int tid = threadIdx.x;
    if (tid < HIDDEN) w_s[tid] = fc_w[tid];
    __syncthreads();

    int b = blockIdx.y;
    int n = blockIdx.x * 256 + tid;
    const __nv_bfloat16* hhi = &g_hp[0][0][((size_t)b * NNPOS + n) * 64];
    const __nv_bfloat16* hlo = &g_hp[0][1][((size_t)b * NNPOS + n) * 64];
    float acc = fc_b[0];
    #pragma unroll
    for (int ch = 0; ch < HIDDEN; ch++)
        acc += (__bfloat162float(hhi[ch]) + __bfloat162float(hlo[ch])) * w_s[ch];

    #pragma unroll
    for (int t = 0; t < TSTEPS; t++)
        out[((size_t)b * TSTEPS + t) * NNPOS + n] = acc;
}

extern "C" void kernel_launch(void* const* d_in, const int* in_sizes, int n_in,
                              void* d_out, int out_size) {
    const float* x      = (const float*)d_in[0];  // [16,16,4096,1]
    const float* conv_w = (const float*)d_in[1];  // [256,65,3,3]
    const float* conv_b = (const float*)d_in[2];  // [256]
    const float* fc_w   = (const float*)d_in[3];  // [1,64,1,1]
    const float* fc_b   = (const float*)d_in[4];  // [1]
    float* out = (float*)d_out;                   // [16,16,4096,1]

    cudaFuncSetAttribute(lstm_persist, cudaFuncAttributeMaxDynamicSharedMemorySize, SMEM_BYTES);

    repack_img<<<(2 * 128 * 192 + 255) / 256, 256>>>(conv_w);
    zero_state<<<1024, 256>>>();

    lstm_persist<<<dim3(GROUP_CTAS, BATCH), NTHREADS, SMEM_BYTES>>>(x, conv_w, conv_b);

    fc_kernel<<<dim3(NNPOS / 256, BATCH), 256>>>(fc_w, fc_b, out);
}

// round 17
// speedup vs baseline: 1.2047x; 1.0001x over previous
#include <cuda_runtime.h>
#include <cuda_bf16.h>
#include <math.h>

#define HIDDEN 64
#define BATCH  16
#define TSTEPS 16
#define NNPOS  4096
#define TILE_P 128
#define NTHREADS 512
#define GROUP_CTAS 8             // CTAs per batch group

typedef unsigned int u32;

// ---- smem layout (bytes) ----
#define A_STRIDE 144                 // 64 bf16 = 128B padded to 144 (conflict-free)
#define B_STRIDE 400                 // 192 bf16 = 384B padded to 400
#define APLANE2  (136 * A_STRIDE)    // 19584: 4 groups x 34 private rows (halo duplicated)
#define ABUF     (2 * APLANE2)       // 39168 (hi+lo planes)
#define OFF_A    0                   // 2 buffers
#define OFF_B    (2 * ABUF)          // 78336
#define BPLANE   (128 * B_STRIDE)    // 51200
#define OFF_WX   (OFF_B + 2 * BPLANE)   // 180736; 128*3 floats
#define OFF_BIAS (OFF_WX + 1536)        // 182272; 128 floats
#define SMEM_BYTES (OFF_BIAS + 512)     // 182784 -> 1 CTA/SM

// ---- persistent scratch ----
__device__ __align__(16) __nv_bfloat16 g_wimg[2 * 2 * 128 * 192];
__device__ __align__(16) __nv_bfloat16 g_hp[2][2][(size_t)BATCH * NNPOS * HIDDEN]; // [buf][plane][(b*NN+p)*64+ch]
__device__ __align__(16) float         g_c[(size_t)BATCH * NNPOS * HIDDEN];
__device__ int          g_cnt[BATCH * 32];
__device__ volatile int g_gen[BATCH * 32];

__device__ __forceinline__ u32 smem_u32(const void* p) {
    u32 a; asm("{ .reg .u64 t; cvta.to.shared.u64 t, %1; cvt.u32.u64 %0, t; }" : "=r"(a) : "l"(p));
    return a;
}

__device__ __forceinline__ float frcp(float x) {
    float r; asm("rcp.approx.f32 %0, %1;" : "=f"(r) : "f"(x)); return r;
}

// Eigen-style rational tanh: numerator/denominator, FMA-only; |x| clamp 7.9988.
__device__ __forceinline__ void tanh_nd(float x, float& n, float& d) {
    x = fminf(fmaxf(x, -7.99881172f), 7.99881172f);
    float x2 = x * x;
    float p = -2.76076847742355e-16f;
    p = fmaf(p, x2, 2.00018790482477e-13f);
    p = fmaf(p, x2, -8.60467152213735e-11f);
    p = fmaf(p, x2, 5.12229709037114e-08f);
    p = fmaf(p, x2, 1.48572235717979e-05f);
    p = fmaf(p, x2, 6.37261928875436e-04f);
    p = fmaf(p, x2, 4.89352455891786e-03f);
    n = x * p;
    float q = 1.19825839466702e-06f;
    q = fmaf(q, x2, 1.18534705686654e-04f);
    q = fmaf(q, x2, 2.26843463243900e-03f);
    q = fmaf(q, x2, 4.89352518554385e-03f);
    d = q;
}

// 8 reciprocals with ONE rcp.approx (product tree); dens in [0.0049, ~1].
__device__ __forceinline__ void rcp8(const float* d, float* inv) {
    float q01 = d[0] * d[1], q23 = d[2] * d[3], q45 = d[4] * d[5], q67 = d[6] * d[7];
    float q0123 = q01 * q23, q4567 = q45 * q67;
    float r = frcp(q0123 * q4567);
    float r0123 = r * q4567, r4567 = r * q0123;
    float r01 = r0123 * q23, r23 = r0123 * q01, r45 = r4567 * q67, r67 = r4567 * q45;
    inv[0] = r01 * d[1]; inv[1] = r01 * d[0];
    inv[2] = r23 * d[3]; inv[3] = r23 * d[2];
    inv[4] = r45 * d[5]; inv[5] = r45 * d[4];
    inv[6] = r67 * d[7]; inv[7] = r67 * d[6];
}

__device__ __forceinline__ void mma16816(float* c, const u32* a, const u32* bf) {
    asm volatile(
        "mma.sync.aligned.m16n8k16.row.col.f32.bf16.bf16.f32 "
        "{%0,%1,%2,%3},{%4,%5,%6,%7},{%8,%9},{%0,%1,%2,%3};"
        : "+f"(c[0]), "+f"(c[1]), "+f"(c[2]), "+f"(c[3])
        : "r"(a[0]), "r"(a[1]), "r"(a[2]), "r"(a[3]), "r"(bf[0]), "r"(bf[1]));
}

__device__ __forceinline__ void bar_grp(int wm) {
    asm volatile("bar.sync %0, 128;" :: "r"(wm + 1) : "memory");
}

// group prefetch: 34 private rows (2 planes x 8 chunks) via cp.async.cg (L2-only)
__device__ __forceinline__ void prefetchA_grp(u32 sbase, int buf, int wm, int b,
                                              int p0, int rd, int gtid) {
    for (int m = gtid; m < 544; m += 128) {
        int pl = m / 272, rr = (m % 272) >> 3, c = m & 7;
        int pos = p0 + wm * 32 - 1 + rr;
        bool ok = (pos >= 0 && pos < NNPOS);
        int posc = ok ? pos : 0;
        const void* src = (const char*)&g_hp[rd][pl][((size_t)b * NNPOS + posc) * 64] + c * 16;
        u32 dst = sbase + OFF_A + buf * ABUF + pl * APLANE2 + (wm * 34 + rr) * A_STRIDE + c * 16;
        int sz = ok ? 16 : 0;
        asm volatile("cp.async.cg.shared.global [%0], [%1], 16, %2;" :: "r"(dst), "l"(src), "r"(sz));
    }
    asm volatile("cp.async.commit_group;" ::: "memory");
}

__device__ __forceinline__ void group_barrier(int b) {
    __syncthreads();
    if (threadIdx.x == 0) {
        __threadfence();
        int idx = b * 32;
        int gen = g_gen[idx];
        if (atomicAdd(&g_cnt[idx], 1) == GROUP_CTAS - 1) {
            g_cnt[idx] = 0;
            __threadfence();
            g_gen[idx] = gen + 1;
        } else {
            while (g_gen[idx] == gen) { }
        }
        __threadfence();
    }
    __syncthreads();
}

// ---- setup: weight image ----
__global__ void repack_img(const float* __restrict__ conv_w) {
    int idx = blockIdx.x * blockDim.x + threadIdx.x;
    if (idx >= 2 * 128 * 192) return;
    int hs  = idx / 24576;
    int rem = idx % 24576;
    int n = rem / 192, k = rem % 192;
    int gate = (n >> 3) & 3;
    int chl  = (n >> 5) * 8 + (n & 7);
    int oc = gate * 64 + hs * 32 + chl;
    int kh = k / 64, ic = k % 64;
    float w = conv_w[((oc * 65 + (ic + 1)) * 3 + kh) * 3 + 1];
    __nv_bfloat16 whi = __float2bfloat16(w);
    __nv_bfloat16 wlo = __float2bfloat16(w - __bfloat162float(whi));
    g_wimg[((size_t)(hs * 2 + 0) * 128 + n) * 192 + k] = whi;
    g_wimg[((size_t)(hs * 2 + 1) * 128 + n) * 192 + k] = wlo;
}

__global__ void zero_state() {
    size_t i = (size_t)blockIdx.x * blockDim.x + threadIdx.x;
    size_t stride = (size_t)gridDim.x * blockDim.x;
    const size_t nc = (size_t)BATCH * NNPOS * HIDDEN;
    for (size_t j = i; j < nc; j += stride) g_c[j] = 0.f;
    u32* h0 = (u32*)&g_hp[0][0][0];            // both planes of buf0 contiguous
    for (size_t j = i; j < nc; j += stride) h0[j] = 0u;
    if (i < BATCH * 32) { g_cnt[i] = 0; g_gen[i] = 0; }
}

// ---- persistent kernel: 128 CTAs (1/SM), staggered free-running 4-warp groups ----
__global__ void __launch_bounds__(NTHREADS, 1)
lstm_persist(const float* __restrict__ x, const float* __restrict__ conv_w,
             const float* __restrict__ conv_b) {
    extern __shared__ unsigned char sm[];
    const u32 sbase = smem_u32(sm);
    const int tid = threadIdx.x, wid = tid >> 5, lane = tid & 31;
    const int g = lane >> 2, tq = lane & 3;
    const int b  = blockIdx.y;
    const int j  = blockIdx.x;
    const int hs = j >> 2, tband = j & 3;
    const int wm = wid >> 2, wn = wid & 3;
    const int gtid = tid & 127;

    // ---- stage B once ----
    {
        const uint4* src = (const uint4*)(g_wimg + (size_t)hs * 2 * 128 * 192);
        #pragma unroll
        for (int m = tid; m < 2 * 128 * 24; m += NTHREADS) {
            int pl = m / 3072, r = (m % 3072) / 24, c = m % 24;
            *(uint4*)(sm + OFF_B + pl * BPLANE + r * B_STRIDE + c * 16) = src[m];
        }
    }
    // ---- stage bias/wx once ----
    if (tid < 128) {
        int n = tid;
        int gate = (n >> 3) & 3;
        int chl  = (n >> 5) * 8 + (n & 7);
        int oc = gate * 64 + hs * 32 + chl;
        ((float*)(sm + OFF_BIAS))[n] = conv_b[oc];
        #pragma unroll
        for (int kh = 0; kh < 3; kh++)
            ((float*)(sm + OFF_WX))[n * 3 + kh] = conv_w[((oc * 65 + 0) * 3 + kh) * 3 + 1];
    }
    __syncthreads();

    const float* wxs = (const float*)(sm + OFF_WX);
    const float* bss = (const float*)(sm + OFF_BIAS);

    #pragma unroll 1
    for (int t = 0; t < TSTEPS; t++) {
        const int rd = t & 1, wr = rd ^ 1;

        // staggered start: group wm begins at item 2*wm (anti-phase across groups)
        {
            const int ii0 = (2 * wm) & 7;
            prefetchA_grp(sbase, 0, wm, b, (tband * 8 + ii0) * TILE_P, rd, gtid);
        }

        #pragma unroll 1
        for (int i = 0; i < 8; i++) {
            const int ii = (i + 2 * wm) & 7;          // rotated item order per group
            const int p0 = (tband * 8 + ii) * TILE_P;
            const int buf = i & 1;

            asm volatile("cp.async.wait_group 0;" ::: "memory");
            bar_grp(wm);          // group's A(i) fully in smem

            // prefetch next item into the other buffer (its readers all finished
            // before the barrier above; no post-mainloop barrier needed)
            if (i < 7) {
                const int ii_n = (i + 1 + 2 * wm) & 7;
                prefetchA_grp(sbase, buf ^ 1, wm, b, (tband * 8 + ii_n) * TILE_P, rd, gtid);
            }

            // ---- mainloop: warp tile 32x32, fused hi*hi + lo*hi + hi*lo ----
            float C[2][4][4];
            #pragma unroll
            for (int mt = 0; mt < 2; mt++)
                #pragma unroll
                for (int nt = 0; nt < 4; nt++)
                    #pragma unroll
                    for (int r = 0; r < 4; r++) C[mt][nt][r] = 0.f;

            const unsigned char* Arow = sm + OFF_A + buf * ABUF + (wm * 34 + g) * A_STRIDE + tq * 4;
            const unsigned char* Brow = sm + OFF_B + (wn * 32 + g) * B_STRIDE + tq * 4;

            #pragma unroll 1
            for (int kh = 0; kh < 3; kh++) {
                const unsigned char* Akh = Arow + kh * A_STRIDE;
                const unsigned char* Bkh = Brow + kh * 128;
                #pragma unroll
                for (int kk = 0; kk < 4; kk++) {
                    u32 bh[4][2], bl[4][2];
                    #pragma unroll
                    for (int nt = 0; nt < 4; nt++) {
                        const unsigned char* q = Bkh + nt * (8 * B_STRIDE) + kk * 32;
                        bh[nt][0] = *(const u32*)q;
                        bh[nt][1] = *(const u32*)(q + 16);
                        bl[nt][0] = *(const u32*)(q + BPLANE);
                        bl[nt][1] = *(const u32*)(q + BPLANE + 16);
                    }
                    #pragma unroll
                    for (int mt = 0; mt < 2; mt++) {
                        const unsigned char* p = Akh + mt * (16 * A_STRIDE) + kk * 32;
                        u32 ah[4], al[4];
                        ah[0] = *(const u32*)p;
                        ah[1] = *(const u32*)(p + 8 * A_STRIDE);
                        ah[2] = *(const u32*)(p + 16);
                        ah[3] = *(const u32*)(p + 8 * A_STRIDE + 16);
                        al[0] = *(const u32*)(p + APLANE2);
                        al[1] = *(const u32*)(p + APLANE2 + 8 * A_STRIDE);
                        al[2] = *(const u32*)(p + APLANE2 + 16);
                        al[3] = *(const u32*)(p + APLANE2 + 8 * A_STRIDE + 16);
                        #pragma unroll
                        for (int nt = 0; nt < 4; nt++) mma16816(C[mt][nt], ah, bh[nt]);
                        #pragma unroll
                        for (int nt = 0; nt < 4; nt++) mma16816(C[mt][nt], al, bh[nt]);
                        #pragma unroll
                        for (int nt = 0; nt < 4; nt++) mma16816(C[mt][nt], ah, bl[nt]);
                    }
                }
            }

            // ---- epilogue: MUFU-free gates (rational tanh + batched rcp) ----
            const float* xb = x + ((size_t)b * TSTEPS + t) * NNPOS;
            #pragma unroll
            for (int mt = 0; mt < 2; mt++) {
                #pragma unroll
                for (int rh = 0; rh < 2; rh++) {
                    const int prow = wm * 32 + mt * 16 + g + rh * 8;
                    const int pos  = p0 + prow;
                    const float xm1 = (pos >= 1) ? xb[pos - 1] : 0.f;
                    const float x0v = xb[pos];
                    const float xp1 = (pos <= NNPOS - 2) ? xb[pos + 1] : 0.f;
                    const int chl = wn * 8 + 2 * tq;
                    const size_t base = ((size_t)b * NNPOS + pos) * 64 + hs * 32 + chl;
                    float2 cold = *(const float2*)(g_c + base);

                    float vv[2][4];
                    #pragma unroll
                    for (int lsb = 0; lsb < 2; lsb++) {
                        const int nbb = wn * 32 + 2 * tq + lsb;
                        #pragma unroll
                        for (int gate = 0; gate < 4; gate++) {
                            const int ni = nbb + gate * 8;
                            vv[lsb][gate] = C[mt][gate][rh * 2 + lsb] + bss[ni]
                                          + wxs[ni * 3] * xm1 + wxs[ni * 3 + 1] * x0v
                                          + wxs[ni * 3 + 2] * xp1;
                        }
                    }

                    float nn[8], dd[8], inv[8];
                    #pragma unroll
                    for (int lsb = 0; lsb < 2; lsb++) {
                        tanh_nd(0.5f * vv[lsb][0], nn[lsb * 4 + 0], dd[lsb * 4 + 0]);
                        tanh_nd(0.5f * vv[lsb][1], nn[lsb * 4 + 1], dd[lsb * 4 + 1]);
                        tanh_nd(0.5f * vv[lsb][2], nn[lsb * 4 + 2], dd[lsb * 4 + 2]);
                        tanh_nd(vv[lsb][3],        nn[lsb * 4 + 3], dd[lsb * 4 + 3]);
                    }
                    rcp8(dd, inv);

                    float cc[2], so[2];
                    #pragma unroll
                    for (int lsb = 0; lsb < 2; lsb++) {
                        float si = fmaf(nn[lsb * 4 + 0] * inv[lsb * 4 + 0], 0.5f, 0.5f);
                        float sf = fmaf(nn[lsb * 4 + 1] * inv[lsb * 4 + 1], 0.5f, 0.5f);
                        so[lsb]  = fmaf(nn[lsb * 4 + 2] * inv[lsb * 4 + 2], 0.5f, 0.5f);
                        float tg = nn[lsb * 4 + 3] * inv[lsb * 4 + 3];
                        float co = lsb ? cold.y : cold.x;
                        cc[lsb] = sf * co + si * tg;
                    }

                    float nc0, dc0, nc1, dc1;
                    tanh_nd(cc[0], nc0, dc0);
                    tanh_nd(cc[1], nc1, dc1);
                    float rr = frcp(dc0 * dc1);
                    float h0 = so[0] * (nc0 * (dc1 * rr));
                    float h1 = so[1] * (nc1 * (dc0 * rr));

                    *(float2*)(g_c + base) = make_float2(cc[0], cc[1]);
                    __nv_bfloat162 vhi, vlo;
                    vhi.x = __float2bfloat16(h0);
                    vhi.y = __float2bfloat16(h1);
                    vlo.x = __float2bfloat16(h0 - __bfloat162float(vhi.x));
                    vlo.y = __float2bfloat16(h1 - __bfloat162float(vhi.y));
                    *(__nv_bfloat162*)&g_hp[wr][0][base] = vhi;
                    *(__nv_bfloat162*)&g_hp[wr][1][base] = vlo;
                }
            }
        }

        if (t < TSTEPS - 1) group_barrier(b);
    }
}

// ---- final 1x1 conv + broadcast over TS (final h in buf 0) ----
__global__ void __launch_bounds__(256)
fc_kernel(const float* __restrict__ fc_w, const float* __restrict__ fc_b,
          float* __restrict__ out) {
    __shared__ float w_s[HIDDEN];
    int tid = threadIdx.x;
    if (tid < HIDDEN) w_s[tid] = fc_w[tid];
    __syncthreads();

    int b = blockIdx.y;
    int n = blockIdx.x * 256 + tid;
    const __nv_bfloat16* hhi = &g_hp[0][0][((size_t)b * NNPOS + n) * 64];
    const __nv_bfloat16* hlo = &g_hp[0][1][((size_t)b * NNPOS + n) * 64];
    float acc = fc_b[0];
    #pragma unroll
    for (int ch = 0; ch < HIDDEN; ch++)
        acc += (__bfloat162float(hhi[ch]) + __bfloat162float(hlo[ch])) * w_s[ch];

    #pragma unroll
    for (int t = 0; t < TSTEPS; t++)
        out[((size_t)b * TSTEPS + t) * NNPOS + n] = acc;
}

extern "C" void kernel_launch(void* const* d_in, const int* in_sizes, int n_in,
                              void* d_out, int out_size) {
    const float* x      = (const float*)d_in[0];  // [16,16,4096,1]
    const float* conv_w = (const float*)d_in[1];  // [256,65,3,3]
    const float* conv_b = (const float*)d_in[2];  // [256]
    const float* fc_w   = (const float*)d_in[3];  // [1,64,1,1]
    const float* fc_b   = (const float*)d_in[4];  // [1]
    float* out = (float*)d_out;                   // [16,16,4096,1]

    cudaFuncSetAttribute(lstm_persist, cudaFuncAttributeMaxDynamicSharedMemorySize, SMEM_BYTES);

    repack_img<<<(2 * 128 * 192 + 255) / 256, 256>>>(conv_w);
    zero_state<<<1024, 256>>>();

    lstm_persist<<<dim3(GROUP_CTAS, BATCH), NTHREADS, SMEM_BYTES>>>(x, conv_w, conv_b);

    fc_kernel<<<dim3(NNPOS / 256, BATCH), 256>>>(fc_w, fc_b, out);
}